// round 2
// baseline (speedup 1.0000x reference)
#include <cuda_runtime.h>
#include <cstdint>
#include <cstddef>

#define N_NODES 50000
#define DIM_IN  256
#define DIM_HID 256
#define DIM_OUT 128
#define N_HEADS 4

// ---------------- scratch (static device allocations; allowed) -------------
__device__ float g_h   [N_NODES * DIM_HID];   // relu(x@Wp+bp)
__device__ float g_xw0 [N_NODES * DIM_HID];   // h@W0
__device__ float g_num0[N_NODES * DIM_HID];   // softmax numerator accumulator L0
__device__ float g_h1  [N_NODES * DIM_HID];
__device__ float g_xw1 [N_NODES * DIM_OUT];
__device__ float g_num1[N_NODES * DIM_OUT];
__device__ float g_h2  [N_NODES * DIM_OUT];
__device__ float g_o   [N_NODES * DIM_OUT];
__device__ float g_als0[N_NODES * N_HEADS];
__device__ float g_ald0[N_NODES * N_HEADS];
__device__ float g_den0[N_NODES * N_HEADS];
__device__ float g_als1[N_NODES];
__device__ float g_ald1[N_NODES];
__device__ float g_den1[N_NODES];

// ---------------- helpers ---------------------------------------------------
__device__ __forceinline__ float lrelu(float v) { return v > 0.0f ? v : 0.2f * v; }

__device__ __forceinline__ void red_add_v4(float* p, float4 v) {
    asm volatile("red.global.add.v4.f32 [%0], {%1,%2,%3,%4};"
                 :: "l"(p), "f"(v.x), "f"(v.y), "f"(v.z), "f"(v.w) : "memory");
}

// ---------------- GEMM: C[M,N] = epi(A[M,K] @ B[K,N]) ----------------------
// EPI: 0 = none, 1 = +bias, 2 = relu(+bias)
template <int EPI>
__global__ void __launch_bounds__(256) gemm_f32(
    const float* __restrict__ A, const float* __restrict__ B,
    const float* __restrict__ bias, float* __restrict__ C,
    int M, int N, int K)
{
    constexpr int BM = 128, BN = 64, BK = 16;
    __shared__ float As[BK][BM + 4];
    __shared__ float Bs[BK][BN];

    const int tid = threadIdx.x;
    const int m0  = blockIdx.y * BM;
    const int n0  = blockIdx.x * BN;

    // A loader: 2 float4 per thread
    const int a_row0 = tid >> 2;          // 0..63
    const int a_k4   = (tid & 3) * 4;     // 0,4,8,12
    // B loader: 1 float4 per thread
    const int b_row  = tid >> 4;          // 0..15
    const int b_col  = (tid & 15) * 4;    // 0..60

    const int trow = (tid >> 4) * 8;      // 0..120
    const int tcol = (tid & 15) * 4;      // 0..60

    float acc[8][4] = {};

    for (int kt = 0; kt < K; kt += BK) {
        #pragma unroll
        for (int r = 0; r < 2; r++) {
            int row = a_row0 + r * 64;
            int gm  = m0 + row;
            float4 v = make_float4(0.f, 0.f, 0.f, 0.f);
            if (gm < M) v = *(const float4*)&A[(size_t)gm * K + kt + a_k4];
            As[a_k4 + 0][row] = v.x;
            As[a_k4 + 1][row] = v.y;
            As[a_k4 + 2][row] = v.z;
            As[a_k4 + 3][row] = v.w;
        }
        float4 bv = *(const float4*)&B[(size_t)(kt + b_row) * N + n0 + b_col];
        *(float4*)&Bs[b_row][b_col] = bv;
        __syncthreads();

        #pragma unroll
        for (int k = 0; k < BK; k++) {
            float rm[8], rn[4];
            #pragma unroll
            for (int i = 0; i < 8; i++) rm[i] = As[k][trow + i];
            #pragma unroll
            for (int j = 0; j < 4; j++) rn[j] = Bs[k][tcol + j];
            #pragma unroll
            for (int i = 0; i < 8; i++)
                #pragma unroll
                for (int j = 0; j < 4; j++)
                    acc[i][j] = fmaf(rm[i], rn[j], acc[i][j]);
        }
        __syncthreads();
    }

    float bv0 = 0.f, bv1 = 0.f, bv2 = 0.f, bv3 = 0.f;
    if (EPI >= 1) {
        bv0 = bias[n0 + tcol + 0]; bv1 = bias[n0 + tcol + 1];
        bv2 = bias[n0 + tcol + 2]; bv3 = bias[n0 + tcol + 3];
    }
    #pragma unroll
    for (int i = 0; i < 8; i++) {
        int gm = m0 + trow + i;
        if (gm >= M) continue;
        float4 v = make_float4(acc[i][0], acc[i][1], acc[i][2], acc[i][3]);
        if (EPI >= 1) { v.x += bv0; v.y += bv1; v.z += bv2; v.w += bv3; }
        if (EPI == 2) {
            v.x = fmaxf(v.x, 0.f); v.y = fmaxf(v.y, 0.f);
            v.z = fmaxf(v.z, 0.f); v.w = fmaxf(v.w, 0.f);
        }
        *(float4*)&C[(size_t)gm * N + n0 + tcol] = v;
    }
}

// ---------------- attention logits -----------------------------------------
// layer0: als[n,h] = sum_c xw[n, h*64+c] * a_s[h,c]   (warp per node)
__global__ void al0_kernel(const float* __restrict__ xw,
                           const float* __restrict__ a_s,
                           const float* __restrict__ a_d,
                           float* __restrict__ als, float* __restrict__ ald, int n)
{
    int w = (blockIdx.x * blockDim.x + threadIdx.x) >> 5;
    int lane = threadIdx.x & 31;
    if (w >= n) return;
    int head = lane >> 3;
    int sub  = (lane & 7) * 8;
    const float4* xp = (const float4*)&xw[(size_t)w * 256 + lane * 8];
    float4 x0 = xp[0], x1 = xp[1];
    const float4* sp = (const float4*)&a_s[head * 64 + sub];
    const float4* dp = (const float4*)&a_d[head * 64 + sub];
    float4 s0 = sp[0], s1 = sp[1];
    float4 d0 = dp[0], d1 = dp[1];
    float ss = x0.x*s0.x + x0.y*s0.y + x0.z*s0.z + x0.w*s0.w
             + x1.x*s1.x + x1.y*s1.y + x1.z*s1.z + x1.w*s1.w;
    float sd = x0.x*d0.x + x0.y*d0.y + x0.z*d0.z + x0.w*d0.w
             + x1.x*d1.x + x1.y*d1.y + x1.z*d1.z + x1.w*d1.w;
    #pragma unroll
    for (int o = 4; o; o >>= 1) {
        ss += __shfl_xor_sync(0xffffffffu, ss, o);
        sd += __shfl_xor_sync(0xffffffffu, sd, o);
    }
    if ((lane & 7) == 0) {
        als[w * 4 + head] = ss;
        ald[w * 4 + head] = sd;
    }
}

// layer1: single head, C=128 (warp per node)
__global__ void al1_kernel(const float* __restrict__ xw,
                           const float* __restrict__ a_s,
                           const float* __restrict__ a_d,
                           float* __restrict__ als, float* __restrict__ ald, int n)
{
    int w = (blockIdx.x * blockDim.x + threadIdx.x) >> 5;
    int lane = threadIdx.x & 31;
    if (w >= n) return;
    float4 x = *(const float4*)&xw[(size_t)w * 128 + lane * 4];
    float4 s = *(const float4*)&a_s[lane * 4];
    float4 d = *(const float4*)&a_d[lane * 4];
    float ss = x.x*s.x + x.y*s.y + x.z*s.z + x.w*s.w;
    float sd = x.x*d.x + x.y*d.y + x.z*d.z + x.w*d.w;
    #pragma unroll
    for (int o = 16; o; o >>= 1) {
        ss += __shfl_xor_sync(0xffffffffu, ss, o);
        sd += __shfl_xor_sync(0xffffffffu, sd, o);
    }
    if (lane == 0) { als[w] = ss; ald[w] = sd; }
}

// ---------------- self-loop init (also initializes accumulators) -----------
__global__ void init0_kernel(const float* __restrict__ als, const float* __restrict__ ald,
                             const float* __restrict__ xw,
                             float* __restrict__ den, float* __restrict__ num, int n)
{
    int w = (blockIdx.x * blockDim.x + threadIdx.x) >> 5;
    int lane = threadIdx.x & 31;
    if (w >= n) return;
    int head = lane >> 3;
    float ex = expf(lrelu(als[w * 4 + head] + ald[w * 4 + head]));
    if ((lane & 7) == 0) den[w * 4 + head] = ex;
    const float4* xp = (const float4*)&xw[(size_t)w * 256 + lane * 8];
    float4 a = xp[0], b = xp[1];
    a.x *= ex; a.y *= ex; a.z *= ex; a.w *= ex;
    b.x *= ex; b.y *= ex; b.z *= ex; b.w *= ex;
    float4* op = (float4*)&num[(size_t)w * 256 + lane * 8];
    op[0] = a; op[1] = b;
}

__global__ void init1_kernel(const float* __restrict__ als, const float* __restrict__ ald,
                             const float* __restrict__ xw,
                             float* __restrict__ den, float* __restrict__ num, int n)
{
    int w = (blockIdx.x * blockDim.x + threadIdx.x) >> 5;
    int lane = threadIdx.x & 31;
    if (w >= n) return;
    float ex = expf(lrelu(als[w] + ald[w]));
    if (lane == 0) den[w] = ex;
    float4 v = *(const float4*)&xw[(size_t)w * 128 + lane * 4];
    v.x *= ex; v.y *= ex; v.z *= ex; v.w *= ex;
    *(float4*)&num[(size_t)w * 128 + lane * 4] = v;
}

// ---------------- edge pass A: denominators ---------------------------------
__global__ void edgeA0_kernel(const int* __restrict__ src, const int* __restrict__ dst,
                              const float* __restrict__ als, const float* __restrict__ ald,
                              float* __restrict__ den, int E)
{
    int e = blockIdx.x * blockDim.x + threadIdx.x;
    if (e >= E) return;
    int s = src[e], d = dst[e];
    float4 a = *(const float4*)&als[(size_t)s * 4];
    float4 b = *(const float4*)&ald[(size_t)d * 4];
    atomicAdd(&den[(size_t)d * 4 + 0], expf(lrelu(a.x + b.x)));
    atomicAdd(&den[(size_t)d * 4 + 1], expf(lrelu(a.y + b.y)));
    atomicAdd(&den[(size_t)d * 4 + 2], expf(lrelu(a.z + b.z)));
    atomicAdd(&den[(size_t)d * 4 + 3], expf(lrelu(a.w + b.w)));
}

__global__ void edgeA1_kernel(const int* __restrict__ src, const int* __restrict__ dst,
                              const float* __restrict__ als, const float* __restrict__ ald,
                              float* __restrict__ den, int E)
{
    int e = blockIdx.x * blockDim.x + threadIdx.x;
    if (e >= E) return;
    int s = src[e], d = dst[e];
    atomicAdd(&den[d], expf(lrelu(als[s] + ald[d])));
}

// ---------------- edge pass B: weighted scatter of numerators ---------------
__global__ void edgeB0_kernel(const int* __restrict__ src, const int* __restrict__ dst,
                              const float* __restrict__ als, const float* __restrict__ ald,
                              const float* __restrict__ xw, float* __restrict__ num, int E)
{
    int e = (blockIdx.x * blockDim.x + threadIdx.x) >> 5;
    int lane = threadIdx.x & 31;
    if (e >= E) return;
    int s = src[e], d = dst[e];
    int head = lane >> 3;
    float ex = expf(lrelu(als[(size_t)s * 4 + head] + ald[(size_t)d * 4 + head]));
    const float4* xp = (const float4*)&xw[(size_t)s * 256 + lane * 8];
    float4 a = xp[0], b = xp[1];
    a.x *= ex; a.y *= ex; a.z *= ex; a.w *= ex;
    b.x *= ex; b.y *= ex; b.z *= ex; b.w *= ex;
    float* op = &num[(size_t)d * 256 + lane * 8];
    red_add_v4(op, a);
    red_add_v4(op + 4, b);
}

__global__ void edgeB1_kernel(const int* __restrict__ src, const int* __restrict__ dst,
                              const float* __restrict__ als, const float* __restrict__ ald,
                              const float* __restrict__ xw, float* __restrict__ num, int E)
{
    int e = (blockIdx.x * blockDim.x + threadIdx.x) >> 5;
    int lane = threadIdx.x & 31;
    if (e >= E) return;
    int s = src[e], d = dst[e];
    float ex = expf(lrelu(als[s] + ald[d]));
    float4 v = *(const float4*)&xw[(size_t)s * 128 + lane * 4];
    v.x *= ex; v.y *= ex; v.z *= ex; v.w *= ex;
    red_add_v4(&num[(size_t)d * 128 + lane * 4], v);
}

// ---------------- post: divide + bias + LN (+ residual relu) ---------------
__global__ void post0_kernel(const float* __restrict__ num, const float* __restrict__ den,
                             const float* __restrict__ b0, const float* __restrict__ g0,
                             const float* __restrict__ be0, const float* __restrict__ hres,
                             float* __restrict__ h1, int n)
{
    int w = (blockIdx.x * blockDim.x + threadIdx.x) >> 5;
    int lane = threadIdx.x & 31;
    if (w >= n) return;
    int head = lane >> 3;
    float inv = 1.0f / den[w * 4 + head];
    int c = lane * 8;
    const float4* np = (const float4*)&num[(size_t)w * 256 + c];
    float4 A = np[0], B = np[1];
    float v[8] = {A.x, A.y, A.z, A.w, B.x, B.y, B.z, B.w};
    #pragma unroll
    for (int j = 0; j < 8; j++) v[j] = v[j] * inv + b0[c + j];
    float s = 0.f;
    #pragma unroll
    for (int j = 0; j < 8; j++) s += v[j];
    #pragma unroll
    for (int o = 16; o; o >>= 1) s += __shfl_xor_sync(0xffffffffu, s, o);
    float mu = s * (1.0f / 256.0f);
    float q = 0.f;
    #pragma unroll
    for (int j = 0; j < 8; j++) { float t = v[j] - mu; q += t * t; }
    #pragma unroll
    for (int o = 16; o; o >>= 1) q += __shfl_xor_sync(0xffffffffu, q, o);
    float rs = rsqrtf(q * (1.0f / 256.0f) + 1e-5f);
    #pragma unroll
    for (int j = 0; j < 8; j++) {
        float y = (v[j] - mu) * rs * g0[c + j] + be0[c + j];
        y += hres[(size_t)w * 256 + c + j];
        v[j] = fmaxf(y, 0.0f);
    }
    float4 o0 = make_float4(v[0], v[1], v[2], v[3]);
    float4 o1 = make_float4(v[4], v[5], v[6], v[7]);
    float4* hp = (float4*)&h1[(size_t)w * 256 + c];
    hp[0] = o0; hp[1] = o1;
}

__global__ void post1_kernel(const float* __restrict__ num, const float* __restrict__ den,
                             const float* __restrict__ b1, const float* __restrict__ g1,
                             const float* __restrict__ be1, float* __restrict__ h2, int n)
{
    int w = (blockIdx.x * blockDim.x + threadIdx.x) >> 5;
    int lane = threadIdx.x & 31;
    if (w >= n) return;
    float inv = 1.0f / den[w];
    int c = lane * 4;
    float4 v = *(const float4*)&num[(size_t)w * 128 + c];
    v.x = v.x * inv + b1[c + 0];
    v.y = v.y * inv + b1[c + 1];
    v.z = v.z * inv + b1[c + 2];
    v.w = v.w * inv + b1[c + 3];
    float s = v.x + v.y + v.z + v.w;
    #pragma unroll
    for (int o = 16; o; o >>= 1) s += __shfl_xor_sync(0xffffffffu, s, o);
    float mu = s * (1.0f / 128.0f);
    float q = (v.x-mu)*(v.x-mu) + (v.y-mu)*(v.y-mu) + (v.z-mu)*(v.z-mu) + (v.w-mu)*(v.w-mu);
    #pragma unroll
    for (int o = 16; o; o >>= 1) q += __shfl_xor_sync(0xffffffffu, q, o);
    float rs = rsqrtf(q * (1.0f / 128.0f) + 1e-5f);
    float4 y;
    y.x = (v.x - mu) * rs * g1[c + 0] + be1[c + 0];
    y.y = (v.y - mu) * rs * g1[c + 1] + be1[c + 1];
    y.z = (v.z - mu) * rs * g1[c + 2] + be1[c + 2];
    y.w = (v.w - mu) * rs * g1[c + 3] + be1[c + 3];
    *(float4*)&h2[(size_t)w * 128 + c] = y;
}

// ---------------- final L2 normalize ----------------------------------------
__global__ void norm_kernel(const float* __restrict__ in, float* __restrict__ out, int n)
{
    int w = (blockIdx.x * blockDim.x + threadIdx.x) >> 5;
    int lane = threadIdx.x & 31;
    if (w >= n) return;
    float4 v = *(const float4*)&in[(size_t)w * 128 + lane * 4];
    float q = v.x*v.x + v.y*v.y + v.z*v.z + v.w*v.w;
    #pragma unroll
    for (int o = 16; o; o >>= 1) q += __shfl_xor_sync(0xffffffffu, q, o);
    float sc = 1.0f / fmaxf(sqrtf(q), 1e-12f);
    v.x *= sc; v.y *= sc; v.z *= sc; v.w *= sc;
    *(float4*)&out[(size_t)w * 128 + lane * 4] = v;
}

// ---------------- launch ----------------------------------------------------
static inline int cdiv(int a, int b) { return (a + b - 1) / b; }

extern "C" void kernel_launch(void* const* d_in, const int* in_sizes, int n_in,
                              void* d_out, int out_size)
{
    const float* x   = (const float*)d_in[0];
    const int*   ei  = (const int*)d_in[1];   // JAX x64 disabled: int64 -> int32
    const float* Wp  = (const float*)d_in[2];
    const float* bp  = (const float*)d_in[3];
    const float* W0  = (const float*)d_in[4];
    const float* as0 = (const float*)d_in[5];
    const float* ad0 = (const float*)d_in[6];
    const float* b0  = (const float*)d_in[7];
    const float* W1  = (const float*)d_in[8];
    const float* as1 = (const float*)d_in[9];
    const float* ad1 = (const float*)d_in[10];
    const float* b1  = (const float*)d_in[11];
    const float* g0  = (const float*)d_in[12];
    const float* be0 = (const float*)d_in[13];
    const float* g1  = (const float*)d_in[14];
    const float* be1 = (const float*)d_in[15];
    const float* Wo  = (const float*)d_in[16];
    const float* bo  = (const float*)d_in[17];
    float* out = (float*)d_out;

    const int n = in_sizes[0] / DIM_IN;   // 50000
    const int E = in_sizes[1] / 2;        // 800000
    const int* src = ei;
    const int* dst = ei + E;

    float *p_h, *p_xw0, *p_num0, *p_h1, *p_xw1, *p_num1, *p_h2, *p_o;
    float *p_als0, *p_ald0, *p_den0, *p_als1, *p_ald1, *p_den1;
    cudaGetSymbolAddress((void**)&p_h,    g_h);
    cudaGetSymbolAddress((void**)&p_xw0,  g_xw0);
    cudaGetSymbolAddress((void**)&p_num0, g_num0);
    cudaGetSymbolAddress((void**)&p_h1,   g_h1);
    cudaGetSymbolAddress((void**)&p_xw1,  g_xw1);
    cudaGetSymbolAddress((void**)&p_num1, g_num1);
    cudaGetSymbolAddress((void**)&p_h2,   g_h2);
    cudaGetSymbolAddress((void**)&p_o,    g_o);
    cudaGetSymbolAddress((void**)&p_als0, g_als0);
    cudaGetSymbolAddress((void**)&p_ald0, g_ald0);
    cudaGetSymbolAddress((void**)&p_den0, g_den0);
    cudaGetSymbolAddress((void**)&p_als1, g_als1);
    cudaGetSymbolAddress((void**)&p_ald1, g_ald1);
    cudaGetSymbolAddress((void**)&p_den1, g_den1);

    const dim3 blk(256);
    const int nodeWarpBlocks = cdiv(n * 32, 256);
    const int edgeThreadBlocks = cdiv(E, 256);
    const int edgeWarpBlocks = cdiv(E * 32, 256);

    // 1) h = relu(x @ Wp + bp)
    gemm_f32<2><<<dim3(DIM_HID / 64, cdiv(n, 128)), blk>>>(x, Wp, bp, p_h, n, DIM_HID, DIM_IN);
    // 2) xw0 = h @ W0
    gemm_f32<0><<<dim3(DIM_HID / 64, cdiv(n, 128)), blk>>>(p_h, W0, nullptr, p_xw0, n, DIM_HID, DIM_HID);
    // 3) attention logits layer 0
    al0_kernel<<<nodeWarpBlocks, blk>>>(p_xw0, as0, ad0, p_als0, p_ald0, n);
    // 4) self-loop init (den0/num0 initialized here)
    init0_kernel<<<nodeWarpBlocks, blk>>>(p_als0, p_ald0, p_xw0, p_den0, p_num0, n);
    // 5) denominators over edges
    edgeA0_kernel<<<edgeThreadBlocks, blk>>>(src, dst, p_als0, p_ald0, p_den0, E);
    // 6) weighted numerator scatter
    edgeB0_kernel<<<edgeWarpBlocks, blk>>>(src, dst, p_als0, p_ald0, p_xw0, p_num0, E);
    // 7) divide + bias + LN + residual + relu
    post0_kernel<<<nodeWarpBlocks, blk>>>(p_num0, p_den0, b0, g0, be0, p_h, p_h1, n);

    // 8) xw1 = h1 @ W1
    gemm_f32<0><<<dim3(DIM_OUT / 64, cdiv(n, 128)), blk>>>(p_h1, W1, nullptr, p_xw1, n, DIM_OUT, DIM_HID);
    // 9-12) layer 1 attention
    al1_kernel<<<nodeWarpBlocks, blk>>>(p_xw1, as1, ad1, p_als1, p_ald1, n);
    init1_kernel<<<nodeWarpBlocks, blk>>>(p_als1, p_ald1, p_xw1, p_den1, p_num1, n);
    edgeA1_kernel<<<edgeThreadBlocks, blk>>>(src, dst, p_als1, p_ald1, p_den1, E);
    edgeB1_kernel<<<edgeWarpBlocks, blk>>>(src, dst, p_als1, p_ald1, p_xw1, p_num1, E);
    // 13) divide + bias + LN
    post1_kernel<<<nodeWarpBlocks, blk>>>(p_num1, p_den1, b1, g1, be1, p_h2, n);

    // 14) out = h2 @ Wo + bo
    gemm_f32<1><<<dim3(DIM_OUT / 64, cdiv(n, 128)), blk>>>(p_h2, Wo, bo, p_o, n, DIM_OUT, DIM_OUT);
    // 15) row L2 normalize -> d_out
    norm_kernel<<<nodeWarpBlocks, blk>>>(p_o, out, n);
}

// round 4
// speedup vs baseline: 1.2255x; 1.2255x over previous
#include <cuda_runtime.h>
#include <cuda_bf16.h>
#include <cstdint>
#include <cstddef>

#define N_NODES 50000
#define DIM_IN  256
#define DIM_HID 256
#define DIM_OUT 128
#define N_HEADS 4

// ---------------- scratch (static device allocations; allowed) -------------
__device__ float g_h   [N_NODES * DIM_HID];
__device__ float g_xw0 [N_NODES * DIM_HID];
__device__ float g_num0[N_NODES * DIM_HID];
__device__ float g_h1  [N_NODES * DIM_HID];
__device__ float g_xw1 [N_NODES * DIM_OUT];
__device__ float g_num1[N_NODES * DIM_OUT];
__device__ float g_h2  [N_NODES * DIM_OUT];
__device__ float g_o   [N_NODES * DIM_OUT];
__device__ float g_als0[N_NODES * N_HEADS];
__device__ float g_ald0[N_NODES * N_HEADS];
__device__ float g_den0[N_NODES * N_HEADS];
__device__ float g_als1[N_NODES];
__device__ float g_ald1[N_NODES];
__device__ float g_den1[N_NODES];

// bf16 hi/lo splits
__device__ __nv_bfloat16 g_xhi [N_NODES * DIM_IN];
__device__ __nv_bfloat16 g_xlo [N_NODES * DIM_IN];
__device__ __nv_bfloat16 g_hhi [N_NODES * DIM_HID];
__device__ __nv_bfloat16 g_hlo [N_NODES * DIM_HID];
__device__ __nv_bfloat16 g_h1hi[N_NODES * DIM_HID];
__device__ __nv_bfloat16 g_h1lo[N_NODES * DIM_HID];
__device__ __nv_bfloat16 g_h2hi[N_NODES * DIM_OUT];
__device__ __nv_bfloat16 g_h2lo[N_NODES * DIM_OUT];
// transposed weights [N][K]
__device__ __nv_bfloat16 g_WpThi[DIM_HID * DIM_IN];
__device__ __nv_bfloat16 g_WpTlo[DIM_HID * DIM_IN];
__device__ __nv_bfloat16 g_W0Thi[DIM_HID * DIM_HID];
__device__ __nv_bfloat16 g_W0Tlo[DIM_HID * DIM_HID];
__device__ __nv_bfloat16 g_W1Thi[DIM_OUT * DIM_HID];
__device__ __nv_bfloat16 g_W1Tlo[DIM_OUT * DIM_HID];
__device__ __nv_bfloat16 g_WoThi[DIM_OUT * DIM_OUT];
__device__ __nv_bfloat16 g_WoTlo[DIM_OUT * DIM_OUT];

// ---------------- helpers ---------------------------------------------------
__device__ __forceinline__ float lrelu(float v) { return v > 0.0f ? v : 0.2f * v; }

__device__ __forceinline__ void red_add_v4(float* p, float4 v) {
    asm volatile("red.global.add.v4.f32 [%0], {%1,%2,%3,%4};"
                 :: "l"(p), "f"(v.x), "f"(v.y), "f"(v.z), "f"(v.w) : "memory");
}

__device__ __forceinline__ void split2(float a, float b, uint32_t& hi, uint32_t& lo) {
    __nv_bfloat16 ah = __float2bfloat16(a), bh = __float2bfloat16(b);
    __nv_bfloat16 al = __float2bfloat16(a - __bfloat162float(ah));
    __nv_bfloat16 bl = __float2bfloat16(b - __bfloat162float(bh));
    hi = (uint32_t)__bfloat16_as_ushort(ah) | ((uint32_t)__bfloat16_as_ushort(bh) << 16);
    lo = (uint32_t)__bfloat16_as_ushort(al) | ((uint32_t)__bfloat16_as_ushort(bl) << 16);
}

__device__ __forceinline__ uint32_t smem_u32(const void* p) {
    uint32_t a;
    asm("{ .reg .u64 t; cvta.to.shared.u64 t, %1; cvt.u32.u64 %0, t; }" : "=r"(a) : "l"(p));
    return a;
}
__device__ __forceinline__ void cp_async16(uint32_t dst, const void* src) {
    asm volatile("cp.async.cg.shared.global [%0], [%1], 16;" :: "r"(dst), "l"(src));
}
#define CP_COMMIT()  asm volatile("cp.async.commit_group;" ::: "memory")
#define CP_WAIT0()   asm volatile("cp.async.wait_group 0;" ::: "memory")

// ---------------- prep kernels ----------------------------------------------
__global__ void split_kernel(const float* __restrict__ in,
                             __nv_bfloat16* __restrict__ hi, __nv_bfloat16* __restrict__ lo, int n4)
{
    int i = blockIdx.x * blockDim.x + threadIdx.x;
    if (i >= n4) return;
    float4 v = ((const float4*)in)[i];
    uint32_t h0, l0, h1, l1;
    split2(v.x, v.y, h0, l0);
    split2(v.z, v.w, h1, l1);
    ((uint2*)hi)[i] = make_uint2(h0, h1);
    ((uint2*)lo)[i] = make_uint2(l0, l1);
}

// W[K][N] -> T_hi/T_lo [N][K]
__global__ void tsplit_kernel(const float* __restrict__ W,
                              __nv_bfloat16* __restrict__ Thi, __nv_bfloat16* __restrict__ Tlo,
                              int K, int N)
{
    int idx = blockIdx.x * blockDim.x + threadIdx.x;
    if (idx >= K * N) return;
    int k = idx / N, nn = idx % N;
    float v = W[idx];
    __nv_bfloat16 h = __float2bfloat16(v);
    __nv_bfloat16 l = __float2bfloat16(v - __bfloat162float(h));
    Thi[(size_t)nn * K + k] = h;
    Tlo[(size_t)nn * K + k] = l;
}

// ---------------- mma.sync split-precision GEMM ------------------------------
// C[M,Ntot] = epi(A @ Bt^T); A hi/lo bf16 [M][K], Bt hi/lo bf16 [Ntot][K].
// EPI: 0 none; 1 +bias; 2 relu(+bias) + emit bf16 hi/lo of C.
// Tiles: BM=128, BN=64, BK=64. 256 threads, 8 warps (warp grid 4x2 over M,N).
// SMEM rows padded to 72 bf16 (144B) -> conflict-free fragment loads.
template <int EPI>
__global__ void __launch_bounds__(256, 1) mm_mma(
    const __nv_bfloat16* __restrict__ Ahi, const __nv_bfloat16* __restrict__ Alo,
    const __nv_bfloat16* __restrict__ Bhi, const __nv_bfloat16* __restrict__ Blo,
    const float* __restrict__ bias, float* __restrict__ C,
    __nv_bfloat16* __restrict__ Chi, __nv_bfloat16* __restrict__ Clo,
    int M, int Ntot, int K)
{
    constexpr int LDE = 72;                 // padded row length in bf16 elems
    constexpr int OFF_AHI = 0;
    constexpr int OFF_ALO = 128 * LDE;      // 9216
    constexpr int OFF_BHI = 2 * 128 * LDE;  // 18432
    constexpr int OFF_BLO = OFF_BHI + 64 * LDE;
    constexpr int STAGE = OFF_BLO + 64 * LDE;  // 27648 elems = 55296 B

    extern __shared__ __nv_bfloat16 sm[];
    const uint32_t sm_base = smem_u32(sm);

    const int tid  = threadIdx.x;
    const int wid  = tid >> 5;
    const int lane = tid & 31;
    const int wm   = wid & 3;               // warp row  (4)
    const int wn   = wid >> 2;              // warp col  (2)
    const int m0   = blockIdx.y * 128;
    const int n0   = blockIdx.x * 64;
    const int nk   = K >> 6;

    auto load_stage = [&](int kc, int st) {
        const int k0 = kc * 64;
        const uint32_t sbase = sm_base + (uint32_t)(st * STAGE) * 2;
        // A: 128 rows x 8 chunks of 16B (hi & lo)
        #pragma unroll
        for (int c = 0; c < 4; c++) {
            int idx = c * 256 + tid;        // 0..1023
            int row = idx >> 3, seg = idx & 7;
            uint32_t doff = (uint32_t)(row * LDE + seg * 8) * 2;
            int gm = m0 + row;
            if (gm < M) {
                cp_async16(sbase + OFF_AHI * 2 + doff, &Ahi[(size_t)gm * K + k0 + seg * 8]);
                cp_async16(sbase + OFF_ALO * 2 + doff, &Alo[(size_t)gm * K + k0 + seg * 8]);
            } else {
                uint4 z = make_uint4(0, 0, 0, 0);
                *(uint4*)(sm + st * STAGE + OFF_AHI + row * LDE + seg * 8) = z;
                *(uint4*)(sm + st * STAGE + OFF_ALO + row * LDE + seg * 8) = z;
            }
        }
        // B: 64 rows x 8 chunks (hi & lo)
        #pragma unroll
        for (int c = 0; c < 2; c++) {
            int idx = c * 256 + tid;        // 0..511
            int row = idx >> 3, seg = idx & 7;
            uint32_t doff = (uint32_t)(row * LDE + seg * 8) * 2;
            const size_t goff = (size_t)(n0 + row) * K + k0 + seg * 8;
            cp_async16(sbase + OFF_BHI * 2 + doff, &Bhi[goff]);
            cp_async16(sbase + OFF_BLO * 2 + doff, &Blo[goff]);
        }
        CP_COMMIT();
    };

    float4 acc[2][4];
    #pragma unroll
    for (int i = 0; i < 2; i++)
        #pragma unroll
        for (int j = 0; j < 4; j++) acc[i][j] = make_float4(0.f, 0.f, 0.f, 0.f);

    load_stage(0, 0);

    for (int kc = 0; kc < nk; kc++) {
        const int st = kc & 1;
        CP_WAIT0();
        __syncthreads();
        if (kc + 1 < nk) load_stage(kc + 1, st ^ 1);

        const uint32_t* sAhi = (const uint32_t*)(sm + st * STAGE + OFF_AHI);
        const uint32_t* sAlo = (const uint32_t*)(sm + st * STAGE + OFF_ALO);
        const uint32_t* sBhi = (const uint32_t*)(sm + st * STAGE + OFF_BHI);
        const uint32_t* sBlo = (const uint32_t*)(sm + st * STAGE + OFF_BLO);

        #pragma unroll
        for (int kk = 0; kk < 4; kk++) {
            const int kb = kk * 16 + (lane & 3) * 2;     // bf16 col
            uint32_t ahi[2][4], alo[2][4], bhi[4][2], blo[4][2];
            #pragma unroll
            for (int mt = 0; mt < 2; mt++) {
                int r = wm * 32 + mt * 16 + (lane >> 2);
                const uint32_t* p = sAhi + r * (LDE / 2) + (kb >> 1);
                ahi[mt][0] = p[0]; ahi[mt][1] = p[8 * (LDE / 2)];
                ahi[mt][2] = p[4]; ahi[mt][3] = p[8 * (LDE / 2) + 4];
                const uint32_t* q = sAlo + r * (LDE / 2) + (kb >> 1);
                alo[mt][0] = q[0]; alo[mt][1] = q[8 * (LDE / 2)];
                alo[mt][2] = q[4]; alo[mt][3] = q[8 * (LDE / 2) + 4];
            }
            #pragma unroll
            for (int nt = 0; nt < 4; nt++) {
                int r = wn * 32 + nt * 8 + (lane >> 2);
                const uint32_t* p = sBhi + r * (LDE / 2) + (kb >> 1);
                bhi[nt][0] = p[0]; bhi[nt][1] = p[4];
                const uint32_t* q = sBlo + r * (LDE / 2) + (kb >> 1);
                blo[nt][0] = q[0]; blo[nt][1] = q[4];
            }
            #pragma unroll
            for (int mt = 0; mt < 2; mt++)
                #pragma unroll
                for (int nt = 0; nt < 4; nt++) {
                    float4& d = acc[mt][nt];
                    asm volatile(
                        "mma.sync.aligned.m16n8k16.row.col.f32.bf16.bf16.f32 "
                        "{%0,%1,%2,%3},{%4,%5,%6,%7},{%8,%9},{%0,%1,%2,%3};"
                        : "+f"(d.x), "+f"(d.y), "+f"(d.z), "+f"(d.w)
                        : "r"(ahi[mt][0]), "r"(ahi[mt][1]), "r"(ahi[mt][2]), "r"(ahi[mt][3]),
                          "r"(bhi[nt][0]), "r"(bhi[nt][1]));
                    asm volatile(
                        "mma.sync.aligned.m16n8k16.row.col.f32.bf16.bf16.f32 "
                        "{%0,%1,%2,%3},{%4,%5,%6,%7},{%8,%9},{%0,%1,%2,%3};"
                        : "+f"(d.x), "+f"(d.y), "+f"(d.z), "+f"(d.w)
                        : "r"(ahi[mt][0]), "r"(ahi[mt][1]), "r"(ahi[mt][2]), "r"(ahi[mt][3]),
                          "r"(blo[nt][0]), "r"(blo[nt][1]));
                    asm volatile(
                        "mma.sync.aligned.m16n8k16.row.col.f32.bf16.bf16.f32 "
                        "{%0,%1,%2,%3},{%4,%5,%6,%7},{%8,%9},{%0,%1,%2,%3};"
                        : "+f"(d.x), "+f"(d.y), "+f"(d.z), "+f"(d.w)
                        : "r"(alo[mt][0]), "r"(alo[mt][1]), "r"(alo[mt][2]), "r"(alo[mt][3]),
                          "r"(bhi[nt][0]), "r"(bhi[nt][1]));
                }
        }
        __syncthreads();
    }

    // ---------------- epilogue ----------------
    #pragma unroll
    for (int mt = 0; mt < 2; mt++) {
        #pragma unroll
        for (int nt = 0; nt < 4; nt++) {
            float4 d = acc[mt][nt];
            int r0  = m0 + wm * 32 + mt * 16 + (lane >> 2);
            int col = n0 + wn * 32 + nt * 8 + (lane & 3) * 2;
            if (EPI >= 1) {
                float bv0 = bias[col], bv1 = bias[col + 1];
                d.x += bv0; d.y += bv1; d.z += bv0; d.w += bv1;
            }
            if (EPI == 2) {
                d.x = fmaxf(d.x, 0.f); d.y = fmaxf(d.y, 0.f);
                d.z = fmaxf(d.z, 0.f); d.w = fmaxf(d.w, 0.f);
            }
            if (r0 < M) {
                *(float2*)&C[(size_t)r0 * Ntot + col] = make_float2(d.x, d.y);
                if (EPI == 2) {
                    uint32_t h, l;
                    split2(d.x, d.y, h, l);
                    *(uint32_t*)&Chi[(size_t)r0 * Ntot + col] = h;
                    *(uint32_t*)&Clo[(size_t)r0 * Ntot + col] = l;
                }
            }
            if (r0 + 8 < M) {
                *(float2*)&C[(size_t)(r0 + 8) * Ntot + col] = make_float2(d.z, d.w);
                if (EPI == 2) {
                    uint32_t h, l;
                    split2(d.z, d.w, h, l);
                    *(uint32_t*)&Chi[(size_t)(r0 + 8) * Ntot + col] = h;
                    *(uint32_t*)&Clo[(size_t)(r0 + 8) * Ntot + col] = l;
                }
            }
        }
    }
}

// ---------------- attention logits -----------------------------------------
__global__ void al0_kernel(const float* __restrict__ xw,
                           const float* __restrict__ a_s,
                           const float* __restrict__ a_d,
                           float* __restrict__ als, float* __restrict__ ald, int n)
{
    int w = (blockIdx.x * blockDim.x + threadIdx.x) >> 5;
    int lane = threadIdx.x & 31;
    if (w >= n) return;
    int head = lane >> 3;
    int sub  = (lane & 7) * 8;
    const float4* xp = (const float4*)&xw[(size_t)w * 256 + lane * 8];
    float4 x0 = xp[0], x1 = xp[1];
    const float4* sp = (const float4*)&a_s[head * 64 + sub];
    const float4* dp = (const float4*)&a_d[head * 64 + sub];
    float4 s0 = sp[0], s1 = sp[1];
    float4 d0 = dp[0], d1 = dp[1];
    float ss = x0.x*s0.x + x0.y*s0.y + x0.z*s0.z + x0.w*s0.w
             + x1.x*s1.x + x1.y*s1.y + x1.z*s1.z + x1.w*s1.w;
    float sd = x0.x*d0.x + x0.y*d0.y + x0.z*d0.z + x0.w*d0.w
             + x1.x*d1.x + x1.y*d1.y + x1.z*d1.z + x1.w*d1.w;
    #pragma unroll
    for (int o = 4; o; o >>= 1) {
        ss += __shfl_xor_sync(0xffffffffu, ss, o);
        sd += __shfl_xor_sync(0xffffffffu, sd, o);
    }
    if ((lane & 7) == 0) {
        als[w * 4 + head] = ss;
        ald[w * 4 + head] = sd;
    }
}

__global__ void al1_kernel(const float* __restrict__ xw,
                           const float* __restrict__ a_s,
                           const float* __restrict__ a_d,
                           float* __restrict__ als, float* __restrict__ ald, int n)
{
    int w = (blockIdx.x * blockDim.x + threadIdx.x) >> 5;
    int lane = threadIdx.x & 31;
    if (w >= n) return;
    float4 x = *(const float4*)&xw[(size_t)w * 128 + lane * 4];
    float4 s = *(const float4*)&a_s[lane * 4];
    float4 d = *(const float4*)&a_d[lane * 4];
    float ss = x.x*s.x + x.y*s.y + x.z*s.z + x.w*s.w;
    float sd = x.x*d.x + x.y*d.y + x.z*d.z + x.w*d.w;
    #pragma unroll
    for (int o = 16; o; o >>= 1) {
        ss += __shfl_xor_sync(0xffffffffu, ss, o);
        sd += __shfl_xor_sync(0xffffffffu, sd, o);
    }
    if (lane == 0) { als[w] = ss; ald[w] = sd; }
}

// ---------------- self-loop init --------------------------------------------
__global__ void init0_kernel(const float* __restrict__ als, const float* __restrict__ ald,
                             const float* __restrict__ xw,
                             float* __restrict__ den, float* __restrict__ num, int n)
{
    int w = (blockIdx.x * blockDim.x + threadIdx.x) >> 5;
    int lane = threadIdx.x & 31;
    if (w >= n) return;
    int head = lane >> 3;
    float ex = expf(lrelu(als[w * 4 + head] + ald[w * 4 + head]));
    if ((lane & 7) == 0) den[w * 4 + head] = ex;
    const float4* xp = (const float4*)&xw[(size_t)w * 256 + lane * 8];
    float4 a = xp[0], b = xp[1];
    a.x *= ex; a.y *= ex; a.z *= ex; a.w *= ex;
    b.x *= ex; b.y *= ex; b.z *= ex; b.w *= ex;
    float4* op = (float4*)&num[(size_t)w * 256 + lane * 8];
    op[0] = a; op[1] = b;
}

__global__ void init1_kernel(const float* __restrict__ als, const float* __restrict__ ald,
                             const float* __restrict__ xw,
                             float* __restrict__ den, float* __restrict__ num, int n)
{
    int w = (blockIdx.x * blockDim.x + threadIdx.x) >> 5;
    int lane = threadIdx.x & 31;
    if (w >= n) return;
    float ex = expf(lrelu(als[w] + ald[w]));
    if (lane == 0) den[w] = ex;
    float4 v = *(const float4*)&xw[(size_t)w * 128 + lane * 4];
    v.x *= ex; v.y *= ex; v.z *= ex; v.w *= ex;
    *(float4*)&num[(size_t)w * 128 + lane * 4] = v;
}

// ---------------- edge pass A: denominators ---------------------------------
__global__ void edgeA0_kernel(const int* __restrict__ src, const int* __restrict__ dst,
                              const float* __restrict__ als, const float* __restrict__ ald,
                              float* __restrict__ den, int E)
{
    int e = blockIdx.x * blockDim.x + threadIdx.x;
    if (e >= E) return;
    int s = src[e], d = dst[e];
    float4 a = *(const float4*)&als[(size_t)s * 4];
    float4 b = *(const float4*)&ald[(size_t)d * 4];
    atomicAdd(&den[(size_t)d * 4 + 0], expf(lrelu(a.x + b.x)));
    atomicAdd(&den[(size_t)d * 4 + 1], expf(lrelu(a.y + b.y)));
    atomicAdd(&den[(size_t)d * 4 + 2], expf(lrelu(a.z + b.z)));
    atomicAdd(&den[(size_t)d * 4 + 3], expf(lrelu(a.w + b.w)));
}

__global__ void edgeA1_kernel(const int* __restrict__ src, const int* __restrict__ dst,
                              const float* __restrict__ als, const float* __restrict__ ald,
                              float* __restrict__ den, int E)
{
    int e = blockIdx.x * blockDim.x + threadIdx.x;
    if (e >= E) return;
    int s = src[e], d = dst[e];
    atomicAdd(&den[d], expf(lrelu(als[s] + ald[d])));
}

// ---------------- edge pass B: weighted scatter ------------------------------
__global__ void edgeB0_kernel(const int* __restrict__ src, const int* __restrict__ dst,
                              const float* __restrict__ als, const float* __restrict__ ald,
                              const float* __restrict__ xw, float* __restrict__ num, int E)
{
    int e = (blockIdx.x * blockDim.x + threadIdx.x) >> 5;
    int lane = threadIdx.x & 31;
    if (e >= E) return;
    int s = src[e], d = dst[e];
    int head = lane >> 3;
    float ex = expf(lrelu(als[(size_t)s * 4 + head] + ald[(size_t)d * 4 + head]));
    const float4* xp = (const float4*)&xw[(size_t)s * 256 + lane * 8];
    float4 a = xp[0], b = xp[1];
    a.x *= ex; a.y *= ex; a.z *= ex; a.w *= ex;
    b.x *= ex; b.y *= ex; b.z *= ex; b.w *= ex;
    float* op = &num[(size_t)d * 256 + lane * 8];
    red_add_v4(op, a);
    red_add_v4(op + 4, b);
}

__global__ void edgeB1_kernel(const int* __restrict__ src, const int* __restrict__ dst,
                              const float* __restrict__ als, const float* __restrict__ ald,
                              const float* __restrict__ xw, float* __restrict__ num, int E)
{
    int e = (blockIdx.x * blockDim.x + threadIdx.x) >> 5;
    int lane = threadIdx.x & 31;
    if (e >= E) return;
    int s = src[e], d = dst[e];
    float ex = expf(lrelu(als[s] + ald[d]));
    float4 v = *(const float4*)&xw[(size_t)s * 128 + lane * 4];
    v.x *= ex; v.y *= ex; v.z *= ex; v.w *= ex;
    red_add_v4(&num[(size_t)d * 128 + lane * 4], v);
}

// ---------------- post: divide + bias + LN (+ residual relu) + split --------
__global__ void post0_kernel(const float* __restrict__ num, const float* __restrict__ den,
                             const float* __restrict__ b0, const float* __restrict__ g0,
                             const float* __restrict__ be0, const float* __restrict__ hres,
                             float* __restrict__ h1,
                             __nv_bfloat16* __restrict__ h1hi, __nv_bfloat16* __restrict__ h1lo,
                             int n)
{
    int w = (blockIdx.x * blockDim.x + threadIdx.x) >> 5;
    int lane = threadIdx.x & 31;
    if (w >= n) return;
    int head = lane >> 3;
    float inv = 1.0f / den[w * 4 + head];
    int c = lane * 8;
    const float4* np = (const float4*)&num[(size_t)w * 256 + c];
    float4 A = np[0], B = np[1];
    float v[8] = {A.x, A.y, A.z, A.w, B.x, B.y, B.z, B.w};
    #pragma unroll
    for (int j = 0; j < 8; j++) v[j] = v[j] * inv + b0[c + j];
    float s = 0.f;
    #pragma unroll
    for (int j = 0; j < 8; j++) s += v[j];
    #pragma unroll
    for (int o = 16; o; o >>= 1) s += __shfl_xor_sync(0xffffffffu, s, o);
    float mu = s * (1.0f / 256.0f);
    float q = 0.f;
    #pragma unroll
    for (int j = 0; j < 8; j++) { float t = v[j] - mu; q += t * t; }
    #pragma unroll
    for (int o = 16; o; o >>= 1) q += __shfl_xor_sync(0xffffffffu, q, o);
    float rs = rsqrtf(q * (1.0f / 256.0f) + 1e-5f);
    #pragma unroll
    for (int j = 0; j < 8; j++) {
        float y = (v[j] - mu) * rs * g0[c + j] + be0[c + j];
        y += hres[(size_t)w * 256 + c + j];
        v[j] = fmaxf(y, 0.0f);
    }
    float4* hp = (float4*)&h1[(size_t)w * 256 + c];
    hp[0] = make_float4(v[0], v[1], v[2], v[3]);
    hp[1] = make_float4(v[4], v[5], v[6], v[7]);
    uint32_t hh[4], ll[4];
    #pragma unroll
    for (int p = 0; p < 4; p++) split2(v[2*p], v[2*p+1], hh[p], ll[p]);
    *(uint4*)&h1hi[(size_t)w * 256 + c] = make_uint4(hh[0], hh[1], hh[2], hh[3]);
    *(uint4*)&h1lo[(size_t)w * 256 + c] = make_uint4(ll[0], ll[1], ll[2], ll[3]);
}

__global__ void post1_kernel(const float* __restrict__ num, const float* __restrict__ den,
                             const float* __restrict__ b1, const float* __restrict__ g1,
                             const float* __restrict__ be1, float* __restrict__ h2,
                             __nv_bfloat16* __restrict__ h2hi, __nv_bfloat16* __restrict__ h2lo,
                             int n)
{
    int w = (blockIdx.x * blockDim.x + threadIdx.x) >> 5;
    int lane = threadIdx.x & 31;
    if (w >= n) return;
    float inv = 1.0f / den[w];
    int c = lane * 4;
    float4 v = *(const float4*)&num[(size_t)w * 128 + c];
    v.x = v.x * inv + b1[c + 0];
    v.y = v.y * inv + b1[c + 1];
    v.z = v.z * inv + b1[c + 2];
    v.w = v.w * inv + b1[c + 3];
    float s = v.x + v.y + v.z + v.w;
    #pragma unroll
    for (int o = 16; o; o >>= 1) s += __shfl_xor_sync(0xffffffffu, s, o);
    float mu = s * (1.0f / 128.0f);
    float q = (v.x-mu)*(v.x-mu) + (v.y-mu)*(v.y-mu) + (v.z-mu)*(v.z-mu) + (v.w-mu)*(v.w-mu);
    #pragma unroll
    for (int o = 16; o; o >>= 1) q += __shfl_xor_sync(0xffffffffu, q, o);
    float rs = rsqrtf(q * (1.0f / 128.0f) + 1e-5f);
    float4 y;
    y.x = (v.x - mu) * rs * g1[c + 0] + be1[c + 0];
    y.y = (v.y - mu) * rs * g1[c + 1] + be1[c + 1];
    y.z = (v.z - mu) * rs * g1[c + 2] + be1[c + 2];
    y.w = (v.w - mu) * rs * g1[c + 3] + be1[c + 3];
    *(float4*)&h2[(size_t)w * 128 + c] = y;
    uint32_t h0, l0, h1v, l1;
    split2(y.x, y.y, h0, l0);
    split2(y.z, y.w, h1v, l1);
    *(uint2*)&h2hi[(size_t)w * 128 + c] = make_uint2(h0, h1v);
    *(uint2*)&h2lo[(size_t)w * 128 + c] = make_uint2(l0, l1);
}

// ---------------- final L2 normalize ----------------------------------------
__global__ void norm_kernel(const float* __restrict__ in, float* __restrict__ out, int n)
{
    int w = (blockIdx.x * blockDim.x + threadIdx.x) >> 5;
    int lane = threadIdx.x & 31;
    if (w >= n) return;
    float4 v = *(const float4*)&in[(size_t)w * 128 + lane * 4];
    float q = v.x*v.x + v.y*v.y + v.z*v.z + v.w*v.w;
    #pragma unroll
    for (int o = 16; o; o >>= 1) q += __shfl_xor_sync(0xffffffffu, q, o);
    float sc = 1.0f / fmaxf(sqrtf(q), 1e-12f);
    v.x *= sc; v.y *= sc; v.z *= sc; v.w *= sc;
    *(float4*)&out[(size_t)w * 128 + lane * 4] = v;
}

// ---------------- launch ----------------------------------------------------
static inline int cdiv(int a, int b) { return (a + b - 1) / b; }

extern "C" void kernel_launch(void* const* d_in, const int* in_sizes, int n_in,
                              void* d_out, int out_size)
{
    const float* x   = (const float*)d_in[0];
    const int*   ei  = (const int*)d_in[1];   // int32 edge indices
    const float* Wp  = (const float*)d_in[2];
    const float* bp  = (const float*)d_in[3];
    const float* W0  = (const float*)d_in[4];
    const float* as0 = (const float*)d_in[5];
    const float* ad0 = (const float*)d_in[6];
    const float* b0  = (const float*)d_in[7];
    const float* W1  = (const float*)d_in[8];
    const float* as1 = (const float*)d_in[9];
    const float* ad1 = (const float*)d_in[10];
    const float* b1  = (const float*)d_in[11];
    const float* g0  = (const float*)d_in[12];
    const float* be0 = (const float*)d_in[13];
    const float* g1  = (const float*)d_in[14];
    const float* be1 = (const float*)d_in[15];
    const float* Wo  = (const float*)d_in[16];
    const float* bo  = (const float*)d_in[17];
    float* out = (float*)d_out;

    const int n = in_sizes[0] / DIM_IN;   // 50000
    const int E = in_sizes[1] / 2;        // 800000
    const int* src = ei;
    const int* dst = ei + E;

    float *p_h, *p_xw0, *p_num0, *p_h1, *p_xw1, *p_num1, *p_h2, *p_o;
    float *p_als0, *p_ald0, *p_den0, *p_als1, *p_ald1, *p_den1;
    __nv_bfloat16 *p_xhi, *p_xlo, *p_hhi, *p_hlo, *p_h1hi, *p_h1lo, *p_h2hi, *p_h2lo;
    __nv_bfloat16 *p_WpThi, *p_WpTlo, *p_W0Thi, *p_W0Tlo, *p_W1Thi, *p_W1Tlo, *p_WoThi, *p_WoTlo;
    cudaGetSymbolAddress((void**)&p_h,    g_h);
    cudaGetSymbolAddress((void**)&p_xw0,  g_xw0);
    cudaGetSymbolAddress((void**)&p_num0, g_num0);
    cudaGetSymbolAddress((void**)&p_h1,   g_h1);
    cudaGetSymbolAddress((void**)&p_xw1,  g_xw1);
    cudaGetSymbolAddress((void**)&p_num1, g_num1);
    cudaGetSymbolAddress((void**)&p_h2,   g_h2);
    cudaGetSymbolAddress((void**)&p_o,    g_o);
    cudaGetSymbolAddress((void**)&p_als0, g_als0);
    cudaGetSymbolAddress((void**)&p_ald0, g_ald0);
    cudaGetSymbolAddress((void**)&p_den0, g_den0);
    cudaGetSymbolAddress((void**)&p_als1, g_als1);
    cudaGetSymbolAddress((void**)&p_ald1, g_ald1);
    cudaGetSymbolAddress((void**)&p_den1, g_den1);
    cudaGetSymbolAddress((void**)&p_xhi,  g_xhi);
    cudaGetSymbolAddress((void**)&p_xlo,  g_xlo);
    cudaGetSymbolAddress((void**)&p_hhi,  g_hhi);
    cudaGetSymbolAddress((void**)&p_hlo,  g_hlo);
    cudaGetSymbolAddress((void**)&p_h1hi, g_h1hi);
    cudaGetSymbolAddress((void**)&p_h1lo, g_h1lo);
    cudaGetSymbolAddress((void**)&p_h2hi, g_h2hi);
    cudaGetSymbolAddress((void**)&p_h2lo, g_h2lo);
    cudaGetSymbolAddress((void**)&p_WpThi, g_WpThi);
    cudaGetSymbolAddress((void**)&p_WpTlo, g_WpTlo);
    cudaGetSymbolAddress((void**)&p_W0Thi, g_W0Thi);
    cudaGetSymbolAddress((void**)&p_W0Tlo, g_W0Tlo);
    cudaGetSymbolAddress((void**)&p_W1Thi, g_W1Thi);
    cudaGetSymbolAddress((void**)&p_W1Tlo, g_W1Tlo);
    cudaGetSymbolAddress((void**)&p_WoThi, g_WoThi);
    cudaGetSymbolAddress((void**)&p_WoTlo, g_WoTlo);

    constexpr int SMEM_MM = 2 * 27648 * 2;  // 110592 bytes
    cudaFuncSetAttribute(mm_mma<0>, cudaFuncAttributeMaxDynamicSharedMemorySize, SMEM_MM);
    cudaFuncSetAttribute(mm_mma<1>, cudaFuncAttributeMaxDynamicSharedMemorySize, SMEM_MM);
    cudaFuncSetAttribute(mm_mma<2>, cudaFuncAttributeMaxDynamicSharedMemorySize, SMEM_MM);

    const dim3 blk(256);
    const int nodeWarpBlocks = cdiv(n * 32, 256);
    const int edgeThreadBlocks = cdiv(E, 256);
    const int edgeWarpBlocks = cdiv(E * 32, 256);
    const int mrows = cdiv(n, 128);

    // prep: weight transpose+split, x split
    tsplit_kernel<<<cdiv(DIM_IN * DIM_HID, 256), blk>>>(Wp, p_WpThi, p_WpTlo, DIM_IN, DIM_HID);
    tsplit_kernel<<<cdiv(DIM_HID * DIM_HID, 256), blk>>>(W0, p_W0Thi, p_W0Tlo, DIM_HID, DIM_HID);
    tsplit_kernel<<<cdiv(DIM_HID * DIM_OUT, 256), blk>>>(W1, p_W1Thi, p_W1Tlo, DIM_HID, DIM_OUT);
    tsplit_kernel<<<cdiv(DIM_OUT * DIM_OUT, 256), blk>>>(Wo, p_WoThi, p_WoTlo, DIM_OUT, DIM_OUT);
    split_kernel<<<cdiv(n * DIM_IN / 4, 256), blk>>>(x, p_xhi, p_xlo, n * DIM_IN / 4);

    // 1) h = relu(x @ Wp + bp)  (also emits h hi/lo)
    mm_mma<2><<<dim3(DIM_HID / 64, mrows), blk, SMEM_MM>>>(
        p_xhi, p_xlo, p_WpThi, p_WpTlo, bp, p_h, p_hhi, p_hlo, n, DIM_HID, DIM_IN);
    // 2) xw0 = h @ W0
    mm_mma<0><<<dim3(DIM_HID / 64, mrows), blk, SMEM_MM>>>(
        p_hhi, p_hlo, p_W0Thi, p_W0Tlo, nullptr, p_xw0, nullptr, nullptr, n, DIM_HID, DIM_HID);
    // 3-7) layer 0 attention
    al0_kernel<<<nodeWarpBlocks, blk>>>(p_xw0, as0, ad0, p_als0, p_ald0, n);
    init0_kernel<<<nodeWarpBlocks, blk>>>(p_als0, p_ald0, p_xw0, p_den0, p_num0, n);
    edgeA0_kernel<<<edgeThreadBlocks, blk>>>(src, dst, p_als0, p_ald0, p_den0, E);
    edgeB0_kernel<<<edgeWarpBlocks, blk>>>(src, dst, p_als0, p_ald0, p_xw0, p_num0, E);
    post0_kernel<<<nodeWarpBlocks, blk>>>(p_num0, p_den0, b0, g0, be0, p_h, p_h1, p_h1hi, p_h1lo, n);

    // 8) xw1 = h1 @ W1
    mm_mma<0><<<dim3(DIM_OUT / 64, mrows), blk, SMEM_MM>>>(
        p_h1hi, p_h1lo, p_W1Thi, p_W1Tlo, nullptr, p_xw1, nullptr, nullptr, n, DIM_OUT, DIM_HID);
    // 9-13) layer 1 attention
    al1_kernel<<<nodeWarpBlocks, blk>>>(p_xw1, as1, ad1, p_als1, p_ald1, n);
    init1_kernel<<<nodeWarpBlocks, blk>>>(p_als1, p_ald1, p_xw1, p_den1, p_num1, n);
    edgeA1_kernel<<<edgeThreadBlocks, blk>>>(src, dst, p_als1, p_ald1, p_den1, E);
    edgeB1_kernel<<<edgeWarpBlocks, blk>>>(src, dst, p_als1, p_ald1, p_xw1, p_num1, E);
    post1_kernel<<<nodeWarpBlocks, blk>>>(p_num1, p_den1, b1, g1, be1, p_h2, p_h2hi, p_h2lo, n);

    // 14) o = h2 @ Wo + bo
    mm_mma<1><<<dim3(DIM_OUT / 64, mrows), blk, SMEM_MM>>>(
        p_h2hi, p_h2lo, p_WoThi, p_WoTlo, bo, p_o, nullptr, nullptr, n, DIM_OUT, DIM_OUT);
    // 15) row L2 normalize -> d_out
    norm_kernel<<<nodeWarpBlocks, blk>>>(p_o, out, n);
}

// round 5
// speedup vs baseline: 1.7789x; 1.4516x over previous
#include <cuda_runtime.h>
#include <cuda_bf16.h>
#include <cstdint>
#include <cstddef>

#define N_NODES 50000
#define DIM_IN  256
#define DIM_HID 256
#define DIM_OUT 128
#define N_HEADS 4
#define E_MAX   800000

// ---------------- scratch -----------------------------------------------------
__device__ float g_xw0 [N_NODES * DIM_HID];
__device__ float g_xw1 [N_NODES * DIM_OUT];
__device__ float g_o   [N_NODES * DIM_OUT];
__device__ float g_als0[N_NODES * N_HEADS];
__device__ float g_ald0[N_NODES * N_HEADS];
__device__ float g_als1[N_NODES];
__device__ float g_ald1[N_NODES];

// CSR by destination
__device__ int g_deg   [N_NODES];
__device__ int g_off   [N_NODES];
__device__ int g_cursor[N_NODES];
__device__ int g_csrc  [E_MAX];

// bf16 hi/lo splits
__device__ __nv_bfloat16 g_xhi [N_NODES * DIM_IN];
__device__ __nv_bfloat16 g_xlo [N_NODES * DIM_IN];
__device__ __nv_bfloat16 g_hhi [N_NODES * DIM_HID];
__device__ __nv_bfloat16 g_hlo [N_NODES * DIM_HID];
__device__ __nv_bfloat16 g_h1hi[N_NODES * DIM_HID];
__device__ __nv_bfloat16 g_h1lo[N_NODES * DIM_HID];
__device__ __nv_bfloat16 g_h2hi[N_NODES * DIM_OUT];
__device__ __nv_bfloat16 g_h2lo[N_NODES * DIM_OUT];
// transposed weights [N][K]
__device__ __nv_bfloat16 g_WpThi[DIM_HID * DIM_IN];
__device__ __nv_bfloat16 g_WpTlo[DIM_HID * DIM_IN];
__device__ __nv_bfloat16 g_W0Thi[DIM_HID * DIM_HID];
__device__ __nv_bfloat16 g_W0Tlo[DIM_HID * DIM_HID];
__device__ __nv_bfloat16 g_W1Thi[DIM_OUT * DIM_HID];
__device__ __nv_bfloat16 g_W1Tlo[DIM_OUT * DIM_HID];
__device__ __nv_bfloat16 g_WoThi[DIM_OUT * DIM_OUT];
__device__ __nv_bfloat16 g_WoTlo[DIM_OUT * DIM_OUT];

// ---------------- helpers ------------------------------------------------------
__device__ __forceinline__ float lrelu(float v) { return v > 0.0f ? v : 0.2f * v; }

__device__ __forceinline__ void split2(float a, float b, uint32_t& hi, uint32_t& lo) {
    __nv_bfloat16 ah = __float2bfloat16(a), bh = __float2bfloat16(b);
    __nv_bfloat16 al = __float2bfloat16(a - __bfloat162float(ah));
    __nv_bfloat16 bl = __float2bfloat16(b - __bfloat162float(bh));
    hi = (uint32_t)__bfloat16_as_ushort(ah) | ((uint32_t)__bfloat16_as_ushort(bh) << 16);
    lo = (uint32_t)__bfloat16_as_ushort(al) | ((uint32_t)__bfloat16_as_ushort(bl) << 16);
}

__device__ __forceinline__ float2 bf2_to_f2(uint32_t u) {
    __nv_bfloat162 t = *reinterpret_cast<__nv_bfloat162*>(&u);
    return make_float2(__bfloat162float(t.x), __bfloat162float(t.y));
}

__device__ __forceinline__ uint32_t smem_u32(const void* p) {
    uint32_t a;
    asm("{ .reg .u64 t; cvta.to.shared.u64 t, %1; cvt.u32.u64 %0, t; }" : "=r"(a) : "l"(p));
    return a;
}
__device__ __forceinline__ void cp_async16(uint32_t dst, const void* src) {
    asm volatile("cp.async.cg.shared.global [%0], [%1], 16;" :: "r"(dst), "l"(src));
}
#define CP_COMMIT()  asm volatile("cp.async.commit_group;" ::: "memory")
#define CP_WAIT0()   asm volatile("cp.async.wait_group 0;" ::: "memory")

// ---------------- prep kernels --------------------------------------------------
__global__ void split_kernel(const float* __restrict__ in,
                             __nv_bfloat16* __restrict__ hi, __nv_bfloat16* __restrict__ lo, int n4)
{
    int i = blockIdx.x * blockDim.x + threadIdx.x;
    if (i >= n4) return;
    float4 v = ((const float4*)in)[i];
    uint32_t h0, l0, h1, l1;
    split2(v.x, v.y, h0, l0);
    split2(v.z, v.w, h1, l1);
    ((uint2*)hi)[i] = make_uint2(h0, h1);
    ((uint2*)lo)[i] = make_uint2(l0, l1);
}

__global__ void tsplit_kernel(const float* __restrict__ W,
                              __nv_bfloat16* __restrict__ Thi, __nv_bfloat16* __restrict__ Tlo,
                              int K, int N)
{
    int idx = blockIdx.x * blockDim.x + threadIdx.x;
    if (idx >= K * N) return;
    int k = idx / N, nn = idx % N;
    float v = W[idx];
    __nv_bfloat16 h = __float2bfloat16(v);
    __nv_bfloat16 l = __float2bfloat16(v - __bfloat162float(h));
    Thi[(size_t)nn * K + k] = h;
    Tlo[(size_t)nn * K + k] = l;
}

// ---------------- CSR build ------------------------------------------------------
__global__ void zero_kernel(int* __restrict__ p, int n)
{
    int i = blockIdx.x * blockDim.x + threadIdx.x;
    if (i < n) p[i] = 0;
}

__global__ void hist_kernel(const int* __restrict__ dst, int* __restrict__ deg, int E)
{
    int e = blockIdx.x * blockDim.x + threadIdx.x;
    if (e < E) atomicAdd(&deg[dst[e]], 1);
}

// single-block exclusive scan (50k elements), warp-shuffle based
__global__ void scan_kernel(const int* __restrict__ deg, int* __restrict__ off,
                            int* __restrict__ cursor, int n)
{
    __shared__ int wsum[32];
    __shared__ int carry_sh;
    const int tid = threadIdx.x;
    const int lane = tid & 31;
    const int wid = tid >> 5;
    if (tid == 0) carry_sh = 0;
    __syncthreads();
    for (int base = 0; base < n; base += 1024) {
        int i = base + tid;
        int v = (i < n) ? deg[i] : 0;
        int x = v;
        #pragma unroll
        for (int o = 1; o < 32; o <<= 1) {
            int t = __shfl_up_sync(0xffffffffu, x, o);
            if (lane >= o) x += t;
        }
        if (lane == 31) wsum[wid] = x;
        __syncthreads();
        if (wid == 0) {
            int s = wsum[lane];
            #pragma unroll
            for (int o = 1; o < 32; o <<= 1) {
                int t = __shfl_up_sync(0xffffffffu, s, o);
                if (lane >= o) s += t;
            }
            wsum[lane] = s;
        }
        __syncthreads();
        int warpoff = (wid > 0) ? wsum[wid - 1] : 0;
        int excl = x - v + warpoff + carry_sh;
        if (i < n) { off[i] = excl; cursor[i] = excl; }
        __syncthreads();
        if (tid == 0) carry_sh += wsum[31];
        __syncthreads();
    }
}

__global__ void scatter_kernel(const int* __restrict__ src, const int* __restrict__ dst,
                               int* __restrict__ cursor, int* __restrict__ csrc, int E)
{
    int e = blockIdx.x * blockDim.x + threadIdx.x;
    if (e >= E) return;
    int pos = atomicAdd(&cursor[dst[e]], 1);
    csrc[pos] = src[e];
}

// ---------------- mma.sync split-precision GEMM ---------------------------------
// EPI: 0 none; 1 +bias; 3 relu(+bias), write ONLY bf16 hi/lo of C.
template <int EPI>
__global__ void __launch_bounds__(256, 1) mm_mma(
    const __nv_bfloat16* __restrict__ Ahi, const __nv_bfloat16* __restrict__ Alo,
    const __nv_bfloat16* __restrict__ Bhi, const __nv_bfloat16* __restrict__ Blo,
    const float* __restrict__ bias, float* __restrict__ C,
    __nv_bfloat16* __restrict__ Chi, __nv_bfloat16* __restrict__ Clo,
    int M, int Ntot, int K)
{
    constexpr int LDE = 72;
    constexpr int OFF_AHI = 0;
    constexpr int OFF_ALO = 128 * LDE;
    constexpr int OFF_BHI = 2 * 128 * LDE;
    constexpr int OFF_BLO = OFF_BHI + 64 * LDE;
    constexpr int STAGE = OFF_BLO + 64 * LDE;

    extern __shared__ __nv_bfloat16 sm[];
    const uint32_t sm_base = smem_u32(sm);

    const int tid  = threadIdx.x;
    const int wid  = tid >> 5;
    const int lane = tid & 31;
    const int wm   = wid & 3;
    const int wn   = wid >> 2;
    const int m0   = blockIdx.y * 128;
    const int n0   = blockIdx.x * 64;
    const int nk   = K >> 6;

    auto load_stage = [&](int kc, int st) {
        const int k0 = kc * 64;
        const uint32_t sbase = sm_base + (uint32_t)(st * STAGE) * 2;
        #pragma unroll
        for (int c = 0; c < 4; c++) {
            int idx = c * 256 + tid;
            int row = idx >> 3, seg = idx & 7;
            uint32_t doff = (uint32_t)(row * LDE + seg * 8) * 2;
            int gm = m0 + row;
            if (gm < M) {
                cp_async16(sbase + OFF_AHI * 2 + doff, &Ahi[(size_t)gm * K + k0 + seg * 8]);
                cp_async16(sbase + OFF_ALO * 2 + doff, &Alo[(size_t)gm * K + k0 + seg * 8]);
            } else {
                uint4 z = make_uint4(0, 0, 0, 0);
                *(uint4*)(sm + st * STAGE + OFF_AHI + row * LDE + seg * 8) = z;
                *(uint4*)(sm + st * STAGE + OFF_ALO + row * LDE + seg * 8) = z;
            }
        }
        #pragma unroll
        for (int c = 0; c < 2; c++) {
            int idx = c * 256 + tid;
            int row = idx >> 3, seg = idx & 7;
            uint32_t doff = (uint32_t)(row * LDE + seg * 8) * 2;
            const size_t goff = (size_t)(n0 + row) * K + k0 + seg * 8;
            cp_async16(sbase + OFF_BHI * 2 + doff, &Bhi[goff]);
            cp_async16(sbase + OFF_BLO * 2 + doff, &Blo[goff]);
        }
        CP_COMMIT();
    };

    float4 acc[2][4];
    #pragma unroll
    for (int i = 0; i < 2; i++)
        #pragma unroll
        for (int j = 0; j < 4; j++) acc[i][j] = make_float4(0.f, 0.f, 0.f, 0.f);

    load_stage(0, 0);

    for (int kc = 0; kc < nk; kc++) {
        const int st = kc & 1;
        CP_WAIT0();
        __syncthreads();
        if (kc + 1 < nk) load_stage(kc + 1, st ^ 1);

        const uint32_t* sAhi = (const uint32_t*)(sm + st * STAGE + OFF_AHI);
        const uint32_t* sAlo = (const uint32_t*)(sm + st * STAGE + OFF_ALO);
        const uint32_t* sBhi = (const uint32_t*)(sm + st * STAGE + OFF_BHI);
        const uint32_t* sBlo = (const uint32_t*)(sm + st * STAGE + OFF_BLO);

        #pragma unroll
        for (int kk = 0; kk < 4; kk++) {
            const int kb = kk * 16 + (lane & 3) * 2;
            uint32_t ahi[2][4], alo[2][4], bhi[4][2], blo[4][2];
            #pragma unroll
            for (int mt = 0; mt < 2; mt++) {
                int r = wm * 32 + mt * 16 + (lane >> 2);
                const uint32_t* p = sAhi + r * (LDE / 2) + (kb >> 1);
                ahi[mt][0] = p[0]; ahi[mt][1] = p[8 * (LDE / 2)];
                ahi[mt][2] = p[4]; ahi[mt][3] = p[8 * (LDE / 2) + 4];
                const uint32_t* q = sAlo + r * (LDE / 2) + (kb >> 1);
                alo[mt][0] = q[0]; alo[mt][1] = q[8 * (LDE / 2)];
                alo[mt][2] = q[4]; alo[mt][3] = q[8 * (LDE / 2) + 4];
            }
            #pragma unroll
            for (int nt = 0; nt < 4; nt++) {
                int r = wn * 32 + nt * 8 + (lane >> 2);
                const uint32_t* p = sBhi + r * (LDE / 2) + (kb >> 1);
                bhi[nt][0] = p[0]; bhi[nt][1] = p[4];
                const uint32_t* q = sBlo + r * (LDE / 2) + (kb >> 1);
                blo[nt][0] = q[0]; blo[nt][1] = q[4];
            }
            #pragma unroll
            for (int mt = 0; mt < 2; mt++)
                #pragma unroll
                for (int nt = 0; nt < 4; nt++) {
                    float4& d = acc[mt][nt];
                    asm volatile(
                        "mma.sync.aligned.m16n8k16.row.col.f32.bf16.bf16.f32 "
                        "{%0,%1,%2,%3},{%4,%5,%6,%7},{%8,%9},{%0,%1,%2,%3};"
                        : "+f"(d.x), "+f"(d.y), "+f"(d.z), "+f"(d.w)
                        : "r"(ahi[mt][0]), "r"(ahi[mt][1]), "r"(ahi[mt][2]), "r"(ahi[mt][3]),
                          "r"(bhi[nt][0]), "r"(bhi[nt][1]));
                    asm volatile(
                        "mma.sync.aligned.m16n8k16.row.col.f32.bf16.bf16.f32 "
                        "{%0,%1,%2,%3},{%4,%5,%6,%7},{%8,%9},{%0,%1,%2,%3};"
                        : "+f"(d.x), "+f"(d.y), "+f"(d.z), "+f"(d.w)
                        : "r"(ahi[mt][0]), "r"(ahi[mt][1]), "r"(ahi[mt][2]), "r"(ahi[mt][3]),
                          "r"(blo[nt][0]), "r"(blo[nt][1]));
                    asm volatile(
                        "mma.sync.aligned.m16n8k16.row.col.f32.bf16.bf16.f32 "
                        "{%0,%1,%2,%3},{%4,%5,%6,%7},{%8,%9},{%0,%1,%2,%3};"
                        : "+f"(d.x), "+f"(d.y), "+f"(d.z), "+f"(d.w)
                        : "r"(alo[mt][0]), "r"(alo[mt][1]), "r"(alo[mt][2]), "r"(alo[mt][3]),
                          "r"(bhi[nt][0]), "r"(bhi[nt][1]));
                }
        }
        __syncthreads();
    }

    #pragma unroll
    for (int mt = 0; mt < 2; mt++) {
        #pragma unroll
        for (int nt = 0; nt < 4; nt++) {
            float4 d = acc[mt][nt];
            int r0  = m0 + wm * 32 + mt * 16 + (lane >> 2);
            int col = n0 + wn * 32 + nt * 8 + (lane & 3) * 2;
            if (EPI >= 1) {
                float bv0 = bias[col], bv1 = bias[col + 1];
                d.x += bv0; d.y += bv1; d.z += bv0; d.w += bv1;
            }
            if (EPI == 3) {
                d.x = fmaxf(d.x, 0.f); d.y = fmaxf(d.y, 0.f);
                d.z = fmaxf(d.z, 0.f); d.w = fmaxf(d.w, 0.f);
            }
            if (r0 < M) {
                if (EPI != 3)
                    *(float2*)&C[(size_t)r0 * Ntot + col] = make_float2(d.x, d.y);
                else {
                    uint32_t h, l;
                    split2(d.x, d.y, h, l);
                    *(uint32_t*)&Chi[(size_t)r0 * Ntot + col] = h;
                    *(uint32_t*)&Clo[(size_t)r0 * Ntot + col] = l;
                }
            }
            if (r0 + 8 < M) {
                if (EPI != 3)
                    *(float2*)&C[(size_t)(r0 + 8) * Ntot + col] = make_float2(d.z, d.w);
                else {
                    uint32_t h, l;
                    split2(d.z, d.w, h, l);
                    *(uint32_t*)&Chi[(size_t)(r0 + 8) * Ntot + col] = h;
                    *(uint32_t*)&Clo[(size_t)(r0 + 8) * Ntot + col] = l;
                }
            }
        }
    }
}

// ---------------- attention logits ----------------------------------------------
__global__ void al0_kernel(const float* __restrict__ xw,
                           const float* __restrict__ a_s,
                           const float* __restrict__ a_d,
                           float* __restrict__ als, float* __restrict__ ald, int n)
{
    int w = (blockIdx.x * blockDim.x + threadIdx.x) >> 5;
    int lane = threadIdx.x & 31;
    if (w >= n) return;
    int head = lane >> 3;
    int sub  = (lane & 7) * 8;
    const float4* xp = (const float4*)&xw[(size_t)w * 256 + lane * 8];
    float4 x0 = xp[0], x1 = xp[1];
    const float4* sp = (const float4*)&a_s[head * 64 + sub];
    const float4* dp = (const float4*)&a_d[head * 64 + sub];
    float4 s0 = sp[0], s1 = sp[1];
    float4 d0 = dp[0], d1 = dp[1];
    float ss = x0.x*s0.x + x0.y*s0.y + x0.z*s0.z + x0.w*s0.w
             + x1.x*s1.x + x1.y*s1.y + x1.z*s1.z + x1.w*s1.w;
    float sd = x0.x*d0.x + x0.y*d0.y + x0.z*d0.z + x0.w*d0.w
             + x1.x*d1.x + x1.y*d1.y + x1.z*d1.z + x1.w*d1.w;
    #pragma unroll
    for (int o = 4; o; o >>= 1) {
        ss += __shfl_xor_sync(0xffffffffu, ss, o);
        sd += __shfl_xor_sync(0xffffffffu, sd, o);
    }
    if ((lane & 7) == 0) {
        als[w * 4 + head] = ss;
        ald[w * 4 + head] = sd;
    }
}

__global__ void al1_kernel(const float* __restrict__ xw,
                           const float* __restrict__ a_s,
                           const float* __restrict__ a_d,
                           float* __restrict__ als, float* __restrict__ ald, int n)
{
    int w = (blockIdx.x * blockDim.x + threadIdx.x) >> 5;
    int lane = threadIdx.x & 31;
    if (w >= n) return;
    float4 x = *(const float4*)&xw[(size_t)w * 128 + lane * 4];
    float4 s = *(const float4*)&a_s[lane * 4];
    float4 d = *(const float4*)&a_d[lane * 4];
    float ss = x.x*s.x + x.y*s.y + x.z*s.z + x.w*s.w;
    float sd = x.x*d.x + x.y*d.y + x.z*d.z + x.w*d.w;
    #pragma unroll
    for (int o = 16; o; o >>= 1) {
        ss += __shfl_xor_sync(0xffffffffu, ss, o);
        sd += __shfl_xor_sync(0xffffffffu, sd, o);
    }
    if (lane == 0) { als[w] = ss; ald[w] = sd; }
}

// ---------------- fused GAT layer 0: gather + softmax + LN + residual ----------
__global__ void gat0_kernel(const int* __restrict__ csrc, const int* __restrict__ off,
                            const int* __restrict__ deg,
                            const float* __restrict__ als, const float* __restrict__ ald,
                            const float* __restrict__ xw,
                            const __nv_bfloat16* __restrict__ hhi,
                            const __nv_bfloat16* __restrict__ hlo,
                            const float* __restrict__ b0, const float* __restrict__ g0,
                            const float* __restrict__ be0,
                            __nv_bfloat16* __restrict__ h1hi, __nv_bfloat16* __restrict__ h1lo,
                            int n)
{
    int d = (blockIdx.x * blockDim.x + threadIdx.x) >> 5;
    int lane = threadIdx.x & 31;
    if (d >= n) return;
    const int head = lane >> 3;
    const float aldv = ald[(size_t)d * 4 + head];

    // self loop
    float ex = expf(lrelu(als[(size_t)d * 4 + head] + aldv));
    const float4* xp = (const float4*)&xw[(size_t)d * 256 + lane * 8];
    float4 A = xp[0], B = xp[1];
    float v[8] = {A.x * ex, A.y * ex, A.z * ex, A.w * ex,
                  B.x * ex, B.y * ex, B.z * ex, B.w * ex};
    float den = ex;

    const int start = off[d];
    const int cnt = deg[d];
    for (int e = 0; e < cnt; e++) {
        int s = csrc[start + e];
        float exe = expf(lrelu(als[(size_t)s * 4 + head] + aldv));
        const float4* sp = (const float4*)&xw[(size_t)s * 256 + lane * 8];
        float4 a = sp[0], b = sp[1];
        v[0] += a.x * exe; v[1] += a.y * exe; v[2] += a.z * exe; v[3] += a.w * exe;
        v[4] += b.x * exe; v[5] += b.y * exe; v[6] += b.z * exe; v[7] += b.w * exe;
        den += exe;
    }

    const float inv = 1.0f / den;
    const int c = lane * 8;
    #pragma unroll
    for (int j = 0; j < 8; j++) v[j] = v[j] * inv + b0[c + j];

    float s = 0.f;
    #pragma unroll
    for (int j = 0; j < 8; j++) s += v[j];
    #pragma unroll
    for (int o = 16; o; o >>= 1) s += __shfl_xor_sync(0xffffffffu, s, o);
    float mu = s * (1.0f / 256.0f);
    float q = 0.f;
    #pragma unroll
    for (int j = 0; j < 8; j++) { float t = v[j] - mu; q += t * t; }
    #pragma unroll
    for (int o = 16; o; o >>= 1) q += __shfl_xor_sync(0xffffffffu, q, o);
    float rs = rsqrtf(q * (1.0f / 256.0f) + 1e-5f);

    // residual from hi/lo split of h
    uint4 rh = *(const uint4*)&hhi[(size_t)d * 256 + c];
    uint4 rl = *(const uint4*)&hlo[(size_t)d * 256 + c];
    float2 r0 = bf2_to_f2(rh.x), r1 = bf2_to_f2(rh.y), r2 = bf2_to_f2(rh.z), r3 = bf2_to_f2(rh.w);
    float2 l0 = bf2_to_f2(rl.x), l1 = bf2_to_f2(rl.y), l2 = bf2_to_f2(rl.z), l3 = bf2_to_f2(rl.w);
    float res[8] = {r0.x + l0.x, r0.y + l0.y, r1.x + l1.x, r1.y + l1.y,
                    r2.x + l2.x, r2.y + l2.y, r3.x + l3.x, r3.y + l3.y};

    #pragma unroll
    for (int j = 0; j < 8; j++) {
        float y = (v[j] - mu) * rs * g0[c + j] + be0[c + j] + res[j];
        v[j] = fmaxf(y, 0.0f);
    }
    uint32_t hh[4], ll[4];
    #pragma unroll
    for (int p = 0; p < 4; p++) split2(v[2*p], v[2*p+1], hh[p], ll[p]);
    *(uint4*)&h1hi[(size_t)d * 256 + c] = make_uint4(hh[0], hh[1], hh[2], hh[3]);
    *(uint4*)&h1lo[(size_t)d * 256 + c] = make_uint4(ll[0], ll[1], ll[2], ll[3]);
}

// ---------------- fused GAT layer 1: gather + softmax + LN ---------------------
__global__ void gat1_kernel(const int* __restrict__ csrc, const int* __restrict__ off,
                            const int* __restrict__ deg,
                            const float* __restrict__ als, const float* __restrict__ ald,
                            const float* __restrict__ xw,
                            const float* __restrict__ b1, const float* __restrict__ g1,
                            const float* __restrict__ be1,
                            __nv_bfloat16* __restrict__ h2hi, __nv_bfloat16* __restrict__ h2lo,
                            int n)
{
    int d = (blockIdx.x * blockDim.x + threadIdx.x) >> 5;
    int lane = threadIdx.x & 31;
    if (d >= n) return;
    const float aldv = ald[d];

    float ex = expf(lrelu(als[d] + aldv));
    float4 V = *(const float4*)&xw[(size_t)d * 128 + lane * 4];
    float v[4] = {V.x * ex, V.y * ex, V.z * ex, V.w * ex};
    float den = ex;

    const int start = off[d];
    const int cnt = deg[d];
    for (int e = 0; e < cnt; e++) {
        int s = csrc[start + e];
        float exe = expf(lrelu(als[s] + aldv));
        float4 a = *(const float4*)&xw[(size_t)s * 128 + lane * 4];
        v[0] += a.x * exe; v[1] += a.y * exe; v[2] += a.z * exe; v[3] += a.w * exe;
        den += exe;
    }

    const float inv = 1.0f / den;
    const int c = lane * 4;
    #pragma unroll
    for (int j = 0; j < 4; j++) v[j] = v[j] * inv + b1[c + j];

    float s = v[0] + v[1] + v[2] + v[3];
    #pragma unroll
    for (int o = 16; o; o >>= 1) s += __shfl_xor_sync(0xffffffffu, s, o);
    float mu = s * (1.0f / 128.0f);
    float q = 0.f;
    #pragma unroll
    for (int j = 0; j < 4; j++) { float t = v[j] - mu; q += t * t; }
    #pragma unroll
    for (int o = 16; o; o >>= 1) q += __shfl_xor_sync(0xffffffffu, q, o);
    float rs = rsqrtf(q * (1.0f / 128.0f) + 1e-5f);

    float y0 = (v[0] - mu) * rs * g1[c + 0] + be1[c + 0];
    float y1 = (v[1] - mu) * rs * g1[c + 1] + be1[c + 1];
    float y2 = (v[2] - mu) * rs * g1[c + 2] + be1[c + 2];
    float y3 = (v[3] - mu) * rs * g1[c + 3] + be1[c + 3];
    uint32_t h0, l0, h1v, l1;
    split2(y0, y1, h0, l0);
    split2(y2, y3, h1v, l1);
    *(uint2*)&h2hi[(size_t)d * 128 + c] = make_uint2(h0, h1v);
    *(uint2*)&h2lo[(size_t)d * 128 + c] = make_uint2(l0, l1);
}

// ---------------- final L2 normalize --------------------------------------------
__global__ void norm_kernel(const float* __restrict__ in, float* __restrict__ out, int n)
{
    int w = (blockIdx.x * blockDim.x + threadIdx.x) >> 5;
    int lane = threadIdx.x & 31;
    if (w >= n) return;
    float4 v = *(const float4*)&in[(size_t)w * 128 + lane * 4];
    float q = v.x*v.x + v.y*v.y + v.z*v.z + v.w*v.w;
    #pragma unroll
    for (int o = 16; o; o >>= 1) q += __shfl_xor_sync(0xffffffffu, q, o);
    float sc = 1.0f / fmaxf(sqrtf(q), 1e-12f);
    v.x *= sc; v.y *= sc; v.z *= sc; v.w *= sc;
    *(float4*)&out[(size_t)w * 128 + lane * 4] = v;
}

// ---------------- launch ---------------------------------------------------------
static inline int cdiv(int a, int b) { return (a + b - 1) / b; }

extern "C" void kernel_launch(void* const* d_in, const int* in_sizes, int n_in,
                              void* d_out, int out_size)
{
    const float* x   = (const float*)d_in[0];
    const int*   ei  = (const int*)d_in[1];
    const float* Wp  = (const float*)d_in[2];
    const float* bp  = (const float*)d_in[3];
    const float* W0  = (const float*)d_in[4];
    const float* as0 = (const float*)d_in[5];
    const float* ad0 = (const float*)d_in[6];
    const float* b0  = (const float*)d_in[7];
    const float* W1  = (const float*)d_in[8];
    const float* as1 = (const float*)d_in[9];
    const float* ad1 = (const float*)d_in[10];
    const float* b1  = (const float*)d_in[11];
    const float* g0  = (const float*)d_in[12];
    const float* be0 = (const float*)d_in[13];
    const float* g1  = (const float*)d_in[14];
    const float* be1 = (const float*)d_in[15];
    const float* Wo  = (const float*)d_in[16];
    const float* bo  = (const float*)d_in[17];
    float* out = (float*)d_out;

    const int n = in_sizes[0] / DIM_IN;
    const int E = in_sizes[1] / 2;
    const int* src = ei;
    const int* dst = ei + E;

    float *p_xw0, *p_xw1, *p_o, *p_als0, *p_ald0, *p_als1, *p_ald1;
    int *p_deg, *p_off, *p_cursor, *p_csrc;
    __nv_bfloat16 *p_xhi, *p_xlo, *p_hhi, *p_hlo, *p_h1hi, *p_h1lo, *p_h2hi, *p_h2lo;
    __nv_bfloat16 *p_WpThi, *p_WpTlo, *p_W0Thi, *p_W0Tlo, *p_W1Thi, *p_W1Tlo, *p_WoThi, *p_WoTlo;
    cudaGetSymbolAddress((void**)&p_xw0,  g_xw0);
    cudaGetSymbolAddress((void**)&p_xw1,  g_xw1);
    cudaGetSymbolAddress((void**)&p_o,    g_o);
    cudaGetSymbolAddress((void**)&p_als0, g_als0);
    cudaGetSymbolAddress((void**)&p_ald0, g_ald0);
    cudaGetSymbolAddress((void**)&p_als1, g_als1);
    cudaGetSymbolAddress((void**)&p_ald1, g_ald1);
    cudaGetSymbolAddress((void**)&p_deg,    g_deg);
    cudaGetSymbolAddress((void**)&p_off,    g_off);
    cudaGetSymbolAddress((void**)&p_cursor, g_cursor);
    cudaGetSymbolAddress((void**)&p_csrc,   g_csrc);
    cudaGetSymbolAddress((void**)&p_xhi,  g_xhi);
    cudaGetSymbolAddress((void**)&p_xlo,  g_xlo);
    cudaGetSymbolAddress((void**)&p_hhi,  g_hhi);
    cudaGetSymbolAddress((void**)&p_hlo,  g_hlo);
    cudaGetSymbolAddress((void**)&p_h1hi, g_h1hi);
    cudaGetSymbolAddress((void**)&p_h1lo, g_h1lo);
    cudaGetSymbolAddress((void**)&p_h2hi, g_h2hi);
    cudaGetSymbolAddress((void**)&p_h2lo, g_h2lo);
    cudaGetSymbolAddress((void**)&p_WpThi, g_WpThi);
    cudaGetSymbolAddress((void**)&p_WpTlo, g_WpTlo);
    cudaGetSymbolAddress((void**)&p_W0Thi, g_W0Thi);
    cudaGetSymbolAddress((void**)&p_W0Tlo, g_W0Tlo);
    cudaGetSymbolAddress((void**)&p_W1Thi, g_W1Thi);
    cudaGetSymbolAddress((void**)&p_W1Tlo, g_W1Tlo);
    cudaGetSymbolAddress((void**)&p_WoThi, g_WoThi);
    cudaGetSymbolAddress((void**)&p_WoTlo, g_WoTlo);

    constexpr int SMEM_MM = 2 * 27648 * 2;
    cudaFuncSetAttribute(mm_mma<0>, cudaFuncAttributeMaxDynamicSharedMemorySize, SMEM_MM);
    cudaFuncSetAttribute(mm_mma<1>, cudaFuncAttributeMaxDynamicSharedMemorySize, SMEM_MM);
    cudaFuncSetAttribute(mm_mma<3>, cudaFuncAttributeMaxDynamicSharedMemorySize, SMEM_MM);

    const dim3 blk(256);
    const int nodeWarpBlocks = cdiv(n * 32, 256);
    const int edgeBlocks = cdiv(E, 256);
    const int mrows = cdiv(n, 128);

    // ---- CSR build (independent of GEMMs) ----
    zero_kernel<<<cdiv(n, 256), blk>>>(p_deg, n);
    hist_kernel<<<edgeBlocks, blk>>>(dst, p_deg, E);
    scan_kernel<<<1, 1024>>>(p_deg, p_off, p_cursor, n);
    scatter_kernel<<<edgeBlocks, blk>>>(src, dst, p_cursor, p_csrc, E);

    // ---- prep splits ----
    tsplit_kernel<<<cdiv(DIM_IN * DIM_HID, 256), blk>>>(Wp, p_WpThi, p_WpTlo, DIM_IN, DIM_HID);
    tsplit_kernel<<<cdiv(DIM_HID * DIM_HID, 256), blk>>>(W0, p_W0Thi, p_W0Tlo, DIM_HID, DIM_HID);
    tsplit_kernel<<<cdiv(DIM_HID * DIM_OUT, 256), blk>>>(W1, p_W1Thi, p_W1Tlo, DIM_HID, DIM_OUT);
    tsplit_kernel<<<cdiv(DIM_OUT * DIM_OUT, 256), blk>>>(Wo, p_WoThi, p_WoTlo, DIM_OUT, DIM_OUT);
    split_kernel<<<cdiv(n * DIM_IN / 4, 256), blk>>>(x, p_xhi, p_xlo, n * DIM_IN / 4);

    // 1) h = relu(x @ Wp + bp) -> bf16 hi/lo only
    mm_mma<3><<<dim3(DIM_HID / 64, mrows), blk, SMEM_MM>>>(
        p_xhi, p_xlo, p_WpThi, p_WpTlo, bp, nullptr, p_hhi, p_hlo, n, DIM_HID, DIM_IN);
    // 2) xw0 = h @ W0 (fp32)
    mm_mma<0><<<dim3(DIM_HID / 64, mrows), blk, SMEM_MM>>>(
        p_hhi, p_hlo, p_W0Thi, p_W0Tlo, nullptr, p_xw0, nullptr, nullptr, n, DIM_HID, DIM_HID);
    // 3) logits + 4) fused gather-softmax-LN-residual-relu
    al0_kernel<<<nodeWarpBlocks, blk>>>(p_xw0, as0, ad0, p_als0, p_ald0, n);
    gat0_kernel<<<nodeWarpBlocks, blk>>>(p_csrc, p_off, p_deg, p_als0, p_ald0, p_xw0,
                                         p_hhi, p_hlo, b0, g0, be0, p_h1hi, p_h1lo, n);

    // 5) xw1 = h1 @ W1
    mm_mma<0><<<dim3(DIM_OUT / 64, mrows), blk, SMEM_MM>>>(
        p_h1hi, p_h1lo, p_W1Thi, p_W1Tlo, nullptr, p_xw1, nullptr, nullptr, n, DIM_OUT, DIM_HID);
    // 6) logits + 7) fused layer 1
    al1_kernel<<<nodeWarpBlocks, blk>>>(p_xw1, as1, ad1, p_als1, p_ald1, n);
    gat1_kernel<<<nodeWarpBlocks, blk>>>(p_csrc, p_off, p_deg, p_als1, p_ald1, p_xw1,
                                         b1, g1, be1, p_h2hi, p_h2lo, n);

    // 8) o = h2 @ Wo + bo
    mm_mma<1><<<dim3(DIM_OUT / 64, mrows), blk, SMEM_MM>>>(
        p_h2hi, p_h2lo, p_WoThi, p_WoTlo, bo, p_o, nullptr, nullptr, n, DIM_OUT, DIM_OUT);
    // 9) row L2 normalize -> d_out
    norm_kernel<<<nodeWarpBlocks, blk>>>(p_o, out, n);
}

// round 6
// speedup vs baseline: 1.9486x; 1.0954x over previous
#include <cuda_runtime.h>
#include <cuda_bf16.h>
#include <cstdint>
#include <cstddef>

#define N_NODES 50000
#define DIM_IN  256
#define DIM_HID 256
#define DIM_OUT 128
#define N_HEADS 4
#define E_MAX   800000

// ---------------- scratch -----------------------------------------------------
__device__ float g_xw0 [N_NODES * DIM_HID];
__device__ float g_xw1 [N_NODES * DIM_OUT];
__device__ float g_o   [N_NODES * DIM_OUT];
__device__ float g_als0[N_NODES * N_HEADS];
__device__ float g_ald0[N_NODES * N_HEADS];
__device__ float g_als1[N_NODES];
__device__ float g_ald1[N_NODES];

// CSR by destination
__device__ int g_deg   [N_NODES];
__device__ int g_off   [N_NODES];
__device__ int g_cursor[N_NODES];
__device__ int g_csrc  [E_MAX];

// bf16 hi/lo splits
__device__ __nv_bfloat16 g_xhi [N_NODES * DIM_IN];
__device__ __nv_bfloat16 g_xlo [N_NODES * DIM_IN];
__device__ __nv_bfloat16 g_hhi [N_NODES * DIM_HID];
__device__ __nv_bfloat16 g_hlo [N_NODES * DIM_HID];
__device__ __nv_bfloat16 g_h1hi[N_NODES * DIM_HID];
__device__ __nv_bfloat16 g_h1lo[N_NODES * DIM_HID];
__device__ __nv_bfloat16 g_h2hi[N_NODES * DIM_OUT];
__device__ __nv_bfloat16 g_h2lo[N_NODES * DIM_OUT];
// transposed weights [N][K]
__device__ __nv_bfloat16 g_WpThi[DIM_HID * DIM_IN];
__device__ __nv_bfloat16 g_WpTlo[DIM_HID * DIM_IN];
__device__ __nv_bfloat16 g_W0Thi[DIM_HID * DIM_HID];
__device__ __nv_bfloat16 g_W0Tlo[DIM_HID * DIM_HID];
__device__ __nv_bfloat16 g_W1Thi[DIM_OUT * DIM_HID];
__device__ __nv_bfloat16 g_W1Tlo[DIM_OUT * DIM_HID];
__device__ __nv_bfloat16 g_WoThi[DIM_OUT * DIM_OUT];
__device__ __nv_bfloat16 g_WoTlo[DIM_OUT * DIM_OUT];

// ---------------- helpers ------------------------------------------------------
__device__ __forceinline__ float lrelu(float v) { return v > 0.0f ? v : 0.2f * v; }

__device__ __forceinline__ void split2(float a, float b, uint32_t& hi, uint32_t& lo) {
    __nv_bfloat16 ah = __float2bfloat16(a), bh = __float2bfloat16(b);
    __nv_bfloat16 al = __float2bfloat16(a - __bfloat162float(ah));
    __nv_bfloat16 bl = __float2bfloat16(b - __bfloat162float(bh));
    hi = (uint32_t)__bfloat16_as_ushort(ah) | ((uint32_t)__bfloat16_as_ushort(bh) << 16);
    lo = (uint32_t)__bfloat16_as_ushort(al) | ((uint32_t)__bfloat16_as_ushort(bl) << 16);
}

__device__ __forceinline__ float2 bf2_to_f2(uint32_t u) {
    __nv_bfloat162 t = *reinterpret_cast<__nv_bfloat162*>(&u);
    return make_float2(__bfloat162float(t.x), __bfloat162float(t.y));
}

__device__ __forceinline__ uint32_t smem_u32(const void* p) {
    uint32_t a;
    asm("{ .reg .u64 t; cvta.to.shared.u64 t, %1; cvt.u32.u64 %0, t; }" : "=r"(a) : "l"(p));
    return a;
}
__device__ __forceinline__ void cp_async16(uint32_t dst, const void* src) {
    asm volatile("cp.async.cg.shared.global [%0], [%1], 16;" :: "r"(dst), "l"(src));
}
#define CP_COMMIT()  asm volatile("cp.async.commit_group;" ::: "memory")
#define CP_WAIT0()   asm volatile("cp.async.wait_group 0;" ::: "memory")

__device__ __forceinline__ void ldsm_x4(uint32_t& r0, uint32_t& r1, uint32_t& r2, uint32_t& r3,
                                        uint32_t addr) {
    asm volatile("ldmatrix.sync.aligned.m8n8.x4.shared.b16 {%0,%1,%2,%3}, [%4];"
                 : "=r"(r0), "=r"(r1), "=r"(r2), "=r"(r3) : "r"(addr));
}

// ---------------- prep kernels --------------------------------------------------
__global__ void split_kernel(const float* __restrict__ in,
                             __nv_bfloat16* __restrict__ hi, __nv_bfloat16* __restrict__ lo, int n4)
{
    int i = blockIdx.x * blockDim.x + threadIdx.x;
    if (i >= n4) return;
    float4 v = ((const float4*)in)[i];
    uint32_t h0, l0, h1, l1;
    split2(v.x, v.y, h0, l0);
    split2(v.z, v.w, h1, l1);
    ((uint2*)hi)[i] = make_uint2(h0, h1);
    ((uint2*)lo)[i] = make_uint2(l0, l1);
}

__global__ void tsplit_kernel(const float* __restrict__ W,
                              __nv_bfloat16* __restrict__ Thi, __nv_bfloat16* __restrict__ Tlo,
                              int K, int N)
{
    int idx = blockIdx.x * blockDim.x + threadIdx.x;
    if (idx >= K * N) return;
    int k = idx / N, nn = idx % N;
    float v = W[idx];
    __nv_bfloat16 h = __float2bfloat16(v);
    __nv_bfloat16 l = __float2bfloat16(v - __bfloat162float(h));
    Thi[(size_t)nn * K + k] = h;
    Tlo[(size_t)nn * K + k] = l;
}

// ---------------- CSR build ------------------------------------------------------
__global__ void zero_kernel(int* __restrict__ p, int n)
{
    int i = blockIdx.x * blockDim.x + threadIdx.x;
    if (i < n) p[i] = 0;
}

__global__ void hist_kernel(const int* __restrict__ dst, int* __restrict__ deg, int E)
{
    int i = blockIdx.x * blockDim.x + threadIdx.x;
    int e4 = E >> 2;
    if (i < e4) {
        int4 d = ((const int4*)dst)[i];
        atomicAdd(&deg[d.x], 1);
        atomicAdd(&deg[d.y], 1);
        atomicAdd(&deg[d.z], 1);
        atomicAdd(&deg[d.w], 1);
    } else if (i == e4) {
        for (int t = e4 * 4; t < E; t++) atomicAdd(&deg[dst[t]], 1);
    }
}

__global__ void scan_kernel(const int* __restrict__ deg, int* __restrict__ off,
                            int* __restrict__ cursor, int n)
{
    __shared__ int wsum[32];
    __shared__ int carry_sh;
    const int tid = threadIdx.x;
    const int lane = tid & 31;
    const int wid = tid >> 5;
    if (tid == 0) carry_sh = 0;
    __syncthreads();
    for (int base = 0; base < n; base += 1024) {
        int i = base + tid;
        int v = (i < n) ? deg[i] : 0;
        int x = v;
        #pragma unroll
        for (int o = 1; o < 32; o <<= 1) {
            int t = __shfl_up_sync(0xffffffffu, x, o);
            if (lane >= o) x += t;
        }
        if (lane == 31) wsum[wid] = x;
        __syncthreads();
        if (wid == 0) {
            int s = wsum[lane];
            #pragma unroll
            for (int o = 1; o < 32; o <<= 1) {
                int t = __shfl_up_sync(0xffffffffu, s, o);
                if (lane >= o) s += t;
            }
            wsum[lane] = s;
        }
        __syncthreads();
        int warpoff = (wid > 0) ? wsum[wid - 1] : 0;
        int excl = x - v + warpoff + carry_sh;
        if (i < n) { off[i] = excl; cursor[i] = excl; }
        __syncthreads();
        if (tid == 0) carry_sh += wsum[31];
        __syncthreads();
    }
}

__global__ void scatter_kernel(const int* __restrict__ src, const int* __restrict__ dst,
                               int* __restrict__ cursor, int* __restrict__ csrc, int E)
{
    int i = blockIdx.x * blockDim.x + threadIdx.x;
    int e4 = E >> 2;
    if (i < e4) {
        int4 s = ((const int4*)src)[i];
        int4 d = ((const int4*)dst)[i];
        csrc[atomicAdd(&cursor[d.x], 1)] = s.x;
        csrc[atomicAdd(&cursor[d.y], 1)] = s.y;
        csrc[atomicAdd(&cursor[d.z], 1)] = s.z;
        csrc[atomicAdd(&cursor[d.w], 1)] = s.w;
    } else if (i == e4) {
        for (int t = e4 * 4; t < E; t++)
            csrc[atomicAdd(&cursor[dst[t]], 1)] = src[t];
    }
}

// ---------------- mma.sync split-precision GEMM, BM=128 BN=128 BK=64 ------------
// EPI: 0 none; 1 +bias; 3 relu(+bias) -> bf16 hi/lo only.
template <int EPI>
__global__ void __launch_bounds__(256, 1) mm_mma(
    const __nv_bfloat16* __restrict__ Ahi, const __nv_bfloat16* __restrict__ Alo,
    const __nv_bfloat16* __restrict__ Bhi, const __nv_bfloat16* __restrict__ Blo,
    const float* __restrict__ bias, float* __restrict__ C,
    __nv_bfloat16* __restrict__ Chi, __nv_bfloat16* __restrict__ Clo,
    int M, int Ntot, int K)
{
    constexpr int LDE = 72;
    constexpr int OFF_AHI = 0;
    constexpr int OFF_ALO = 128 * LDE;
    constexpr int OFF_BHI = 2 * 128 * LDE;
    constexpr int OFF_BLO = 3 * 128 * LDE;
    constexpr int STAGE   = 4 * 128 * LDE;   // 36864 bf16

    extern __shared__ __nv_bfloat16 sm[];
    const uint32_t sm_base = smem_u32(sm);

    const int tid  = threadIdx.x;
    const int wid  = tid >> 5;
    const int lane = tid & 31;
    const int wm   = wid & 1;     // 2 warp rows, 64 M-rows each
    const int wn   = wid >> 1;    // 4 warp cols, 32 N-cols each
    const int m0   = blockIdx.y * 128;
    const int n0   = blockIdx.x * 128;
    const int nk   = K >> 6;

    auto load_stage = [&](int kc, int st) {
        const int k0 = kc * 64;
        const uint32_t sbase = sm_base + (uint32_t)(st * STAGE) * 2;
        #pragma unroll
        for (int c = 0; c < 4; c++) {
            int idx = c * 256 + tid;       // 0..1023
            int row = idx >> 3, seg = idx & 7;
            uint32_t doff = (uint32_t)(row * LDE + seg * 8) * 2;
            int gm = m0 + row;
            if (gm < M) {
                cp_async16(sbase + OFF_AHI * 2 + doff, &Ahi[(size_t)gm * K + k0 + seg * 8]);
                cp_async16(sbase + OFF_ALO * 2 + doff, &Alo[(size_t)gm * K + k0 + seg * 8]);
            } else {
                uint4 z = make_uint4(0, 0, 0, 0);
                *(uint4*)(sm + st * STAGE + OFF_AHI + row * LDE + seg * 8) = z;
                *(uint4*)(sm + st * STAGE + OFF_ALO + row * LDE + seg * 8) = z;
            }
            const size_t goff = (size_t)(n0 + row) * K + k0 + seg * 8;
            cp_async16(sbase + OFF_BHI * 2 + doff, &Bhi[goff]);
            cp_async16(sbase + OFF_BLO * 2 + doff, &Blo[goff]);
        }
        CP_COMMIT();
    };

    float4 acc[4][4];
    #pragma unroll
    for (int i = 0; i < 4; i++)
        #pragma unroll
        for (int j = 0; j < 4; j++) acc[i][j] = make_float4(0.f, 0.f, 0.f, 0.f);

    load_stage(0, 0);

    const int l7 = lane & 7;
    const int a_rq = ((lane >> 3) & 1) * 8;   // A: quad row offset
    const int a_kq = (lane >> 4) * 8;         // A: quad col offset
    const int b_rq = (lane >> 4) * 8;         // B: quad row offset
    const int b_kq = ((lane >> 3) & 1) * 8;   // B: quad col offset

    for (int kc = 0; kc < nk; kc++) {
        const int st = kc & 1;
        CP_WAIT0();
        __syncthreads();
        if (kc + 1 < nk) load_stage(kc + 1, st ^ 1);

        const uint32_t sst = sm_base + (uint32_t)(st * STAGE) * 2;

        #pragma unroll
        for (int kk = 0; kk < 4; kk++) {
            const int k0b = kk * 16;
            uint32_t ahi[4][4], alo[4][4], bhi[4][2], blo[4][2];
            #pragma unroll
            for (int mt = 0; mt < 4; mt++) {
                int arow = wm * 64 + mt * 16 + l7 + a_rq;
                uint32_t ad = sst + (uint32_t)(OFF_AHI + arow * LDE + k0b + a_kq) * 2;
                ldsm_x4(ahi[mt][0], ahi[mt][1], ahi[mt][2], ahi[mt][3], ad);
                uint32_t ad2 = sst + (uint32_t)(OFF_ALO + arow * LDE + k0b + a_kq) * 2;
                ldsm_x4(alo[mt][0], alo[mt][1], alo[mt][2], alo[mt][3], ad2);
            }
            #pragma unroll
            for (int np = 0; np < 2; np++) {
                int brow = wn * 32 + np * 16 + l7 + b_rq;
                uint32_t bd = sst + (uint32_t)(OFF_BHI + brow * LDE + k0b + b_kq) * 2;
                ldsm_x4(bhi[2*np][0], bhi[2*np][1], bhi[2*np+1][0], bhi[2*np+1][1], bd);
                uint32_t bd2 = sst + (uint32_t)(OFF_BLO + brow * LDE + k0b + b_kq) * 2;
                ldsm_x4(blo[2*np][0], blo[2*np][1], blo[2*np+1][0], blo[2*np+1][1], bd2);
            }
            #pragma unroll
            for (int mt = 0; mt < 4; mt++)
                #pragma unroll
                for (int nt = 0; nt < 4; nt++) {
                    float4& d = acc[mt][nt];
                    asm volatile(
                        "mma.sync.aligned.m16n8k16.row.col.f32.bf16.bf16.f32 "
                        "{%0,%1,%2,%3},{%4,%5,%6,%7},{%8,%9},{%0,%1,%2,%3};"
                        : "+f"(d.x), "+f"(d.y), "+f"(d.z), "+f"(d.w)
                        : "r"(ahi[mt][0]), "r"(ahi[mt][1]), "r"(ahi[mt][2]), "r"(ahi[mt][3]),
                          "r"(bhi[nt][0]), "r"(bhi[nt][1]));
                    asm volatile(
                        "mma.sync.aligned.m16n8k16.row.col.f32.bf16.bf16.f32 "
                        "{%0,%1,%2,%3},{%4,%5,%6,%7},{%8,%9},{%0,%1,%2,%3};"
                        : "+f"(d.x), "+f"(d.y), "+f"(d.z), "+f"(d.w)
                        : "r"(ahi[mt][0]), "r"(ahi[mt][1]), "r"(ahi[mt][2]), "r"(ahi[mt][3]),
                          "r"(blo[nt][0]), "r"(blo[nt][1]));
                    asm volatile(
                        "mma.sync.aligned.m16n8k16.row.col.f32.bf16.bf16.f32 "
                        "{%0,%1,%2,%3},{%4,%5,%6,%7},{%8,%9},{%0,%1,%2,%3};"
                        : "+f"(d.x), "+f"(d.y), "+f"(d.z), "+f"(d.w)
                        : "r"(alo[mt][0]), "r"(alo[mt][1]), "r"(alo[mt][2]), "r"(alo[mt][3]),
                          "r"(bhi[nt][0]), "r"(bhi[nt][1]));
                }
        }
        __syncthreads();
    }

    #pragma unroll
    for (int mt = 0; mt < 4; mt++) {
        #pragma unroll
        for (int nt = 0; nt < 4; nt++) {
            float4 d = acc[mt][nt];
            int r0  = m0 + wm * 64 + mt * 16 + (lane >> 2);
            int col = n0 + wn * 32 + nt * 8 + (lane & 3) * 2;
            if (EPI >= 1) {
                float bv0 = bias[col], bv1 = bias[col + 1];
                d.x += bv0; d.y += bv1; d.z += bv0; d.w += bv1;
            }
            if (EPI == 3) {
                d.x = fmaxf(d.x, 0.f); d.y = fmaxf(d.y, 0.f);
                d.z = fmaxf(d.z, 0.f); d.w = fmaxf(d.w, 0.f);
            }
            if (r0 < M) {
                if (EPI != 3)
                    *(float2*)&C[(size_t)r0 * Ntot + col] = make_float2(d.x, d.y);
                else {
                    uint32_t h, l;
                    split2(d.x, d.y, h, l);
                    *(uint32_t*)&Chi[(size_t)r0 * Ntot + col] = h;
                    *(uint32_t*)&Clo[(size_t)r0 * Ntot + col] = l;
                }
            }
            if (r0 + 8 < M) {
                if (EPI != 3)
                    *(float2*)&C[(size_t)(r0 + 8) * Ntot + col] = make_float2(d.z, d.w);
                else {
                    uint32_t h, l;
                    split2(d.z, d.w, h, l);
                    *(uint32_t*)&Chi[(size_t)(r0 + 8) * Ntot + col] = h;
                    *(uint32_t*)&Clo[(size_t)(r0 + 8) * Ntot + col] = l;
                }
            }
        }
    }
}

// ---------------- attention logits ----------------------------------------------
__global__ void al0_kernel(const float* __restrict__ xw,
                           const float* __restrict__ a_s,
                           const float* __restrict__ a_d,
                           float* __restrict__ als, float* __restrict__ ald, int n)
{
    int w = (blockIdx.x * blockDim.x + threadIdx.x) >> 5;
    int lane = threadIdx.x & 31;
    if (w >= n) return;
    int head = lane >> 3;
    int sub  = (lane & 7) * 8;
    const float4* xp = (const float4*)&xw[(size_t)w * 256 + lane * 8];
    float4 x0 = xp[0], x1 = xp[1];
    const float4* sp = (const float4*)&a_s[head * 64 + sub];
    const float4* dp = (const float4*)&a_d[head * 64 + sub];
    float4 s0 = sp[0], s1 = sp[1];
    float4 d0 = dp[0], d1 = dp[1];
    float ss = x0.x*s0.x + x0.y*s0.y + x0.z*s0.z + x0.w*s0.w
             + x1.x*s1.x + x1.y*s1.y + x1.z*s1.z + x1.w*s1.w;
    float sd = x0.x*d0.x + x0.y*d0.y + x0.z*d0.z + x0.w*d0.w
             + x1.x*d1.x + x1.y*d1.y + x1.z*d1.z + x1.w*d1.w;
    #pragma unroll
    for (int o = 4; o; o >>= 1) {
        ss += __shfl_xor_sync(0xffffffffu, ss, o);
        sd += __shfl_xor_sync(0xffffffffu, sd, o);
    }
    if ((lane & 7) == 0) {
        als[w * 4 + head] = ss;
        ald[w * 4 + head] = sd;
    }
}

__global__ void al1_kernel(const float* __restrict__ xw,
                           const float* __restrict__ a_s,
                           const float* __restrict__ a_d,
                           float* __restrict__ als, float* __restrict__ ald, int n)
{
    int w = (blockIdx.x * blockDim.x + threadIdx.x) >> 5;
    int lane = threadIdx.x & 31;
    if (w >= n) return;
    float4 x = *(const float4*)&xw[(size_t)w * 128 + lane * 4];
    float4 s = *(const float4*)&a_s[lane * 4];
    float4 d = *(const float4*)&a_d[lane * 4];
    float ss = x.x*s.x + x.y*s.y + x.z*s.z + x.w*s.w;
    float sd = x.x*d.x + x.y*d.y + x.z*d.z + x.w*d.w;
    #pragma unroll
    for (int o = 16; o; o >>= 1) {
        ss += __shfl_xor_sync(0xffffffffu, ss, o);
        sd += __shfl_xor_sync(0xffffffffu, sd, o);
    }
    if (lane == 0) { als[w] = ss; ald[w] = sd; }
}

// ---------------- fused GAT layer 0 ---------------------------------------------
__global__ void gat0_kernel(const int* __restrict__ csrc, const int* __restrict__ off,
                            const int* __restrict__ deg,
                            const float* __restrict__ als, const float* __restrict__ ald,
                            const float* __restrict__ xw,
                            const __nv_bfloat16* __restrict__ hhi,
                            const __nv_bfloat16* __restrict__ hlo,
                            const float* __restrict__ b0, const float* __restrict__ g0,
                            const float* __restrict__ be0,
                            __nv_bfloat16* __restrict__ h1hi, __nv_bfloat16* __restrict__ h1lo,
                            int n)
{
    int d = (blockIdx.x * blockDim.x + threadIdx.x) >> 5;
    int lane = threadIdx.x & 31;
    if (d >= n) return;
    const int head = lane >> 3;
    const float aldv = ald[(size_t)d * 4 + head];

    float ex = expf(lrelu(als[(size_t)d * 4 + head] + aldv));
    const float4* xp = (const float4*)&xw[(size_t)d * 256 + lane * 8];
    float4 A = xp[0], B = xp[1];
    float v[8] = {A.x * ex, A.y * ex, A.z * ex, A.w * ex,
                  B.x * ex, B.y * ex, B.z * ex, B.w * ex};
    float den = ex;

    const int start = off[d];
    const int cnt = deg[d];
    int e = 0;
    for (; e + 2 <= cnt; e += 2) {
        int s0 = csrc[start + e];
        int s1 = csrc[start + e + 1];
        float x0 = als[(size_t)s0 * 4 + head];
        float x1 = als[(size_t)s1 * 4 + head];
        const float4* p0 = (const float4*)&xw[(size_t)s0 * 256 + lane * 8];
        const float4* p1 = (const float4*)&xw[(size_t)s1 * 256 + lane * 8];
        float4 a0 = p0[0], b0v = p0[1];
        float4 a1 = p1[0], b1v = p1[1];
        float e0 = expf(lrelu(x0 + aldv));
        float e1 = expf(lrelu(x1 + aldv));
        v[0] = fmaf(a0.x, e0, v[0]); v[1] = fmaf(a0.y, e0, v[1]);
        v[2] = fmaf(a0.z, e0, v[2]); v[3] = fmaf(a0.w, e0, v[3]);
        v[4] = fmaf(b0v.x, e0, v[4]); v[5] = fmaf(b0v.y, e0, v[5]);
        v[6] = fmaf(b0v.z, e0, v[6]); v[7] = fmaf(b0v.w, e0, v[7]);
        v[0] = fmaf(a1.x, e1, v[0]); v[1] = fmaf(a1.y, e1, v[1]);
        v[2] = fmaf(a1.z, e1, v[2]); v[3] = fmaf(a1.w, e1, v[3]);
        v[4] = fmaf(b1v.x, e1, v[4]); v[5] = fmaf(b1v.y, e1, v[5]);
        v[6] = fmaf(b1v.z, e1, v[6]); v[7] = fmaf(b1v.w, e1, v[7]);
        den += e0 + e1;
    }
    if (e < cnt) {
        int s = csrc[start + e];
        float exe = expf(lrelu(als[(size_t)s * 4 + head] + aldv));
        const float4* sp = (const float4*)&xw[(size_t)s * 256 + lane * 8];
        float4 a = sp[0], b = sp[1];
        v[0] = fmaf(a.x, exe, v[0]); v[1] = fmaf(a.y, exe, v[1]);
        v[2] = fmaf(a.z, exe, v[2]); v[3] = fmaf(a.w, exe, v[3]);
        v[4] = fmaf(b.x, exe, v[4]); v[5] = fmaf(b.y, exe, v[5]);
        v[6] = fmaf(b.z, exe, v[6]); v[7] = fmaf(b.w, exe, v[7]);
        den += exe;
    }

    const float inv = 1.0f / den;
    const int c = lane * 8;
    #pragma unroll
    for (int j = 0; j < 8; j++) v[j] = v[j] * inv + b0[c + j];

    float s = 0.f;
    #pragma unroll
    for (int j = 0; j < 8; j++) s += v[j];
    #pragma unroll
    for (int o = 16; o; o >>= 1) s += __shfl_xor_sync(0xffffffffu, s, o);
    float mu = s * (1.0f / 256.0f);
    float q = 0.f;
    #pragma unroll
    for (int j = 0; j < 8; j++) { float t = v[j] - mu; q += t * t; }
    #pragma unroll
    for (int o = 16; o; o >>= 1) q += __shfl_xor_sync(0xffffffffu, q, o);
    float rs = rsqrtf(q * (1.0f / 256.0f) + 1e-5f);

    uint4 rh = *(const uint4*)&hhi[(size_t)d * 256 + c];
    uint4 rl = *(const uint4*)&hlo[(size_t)d * 256 + c];
    float2 r0 = bf2_to_f2(rh.x), r1 = bf2_to_f2(rh.y), r2 = bf2_to_f2(rh.z), r3 = bf2_to_f2(rh.w);
    float2 l0 = bf2_to_f2(rl.x), l1 = bf2_to_f2(rl.y), l2 = bf2_to_f2(rl.z), l3 = bf2_to_f2(rl.w);
    float res[8] = {r0.x + l0.x, r0.y + l0.y, r1.x + l1.x, r1.y + l1.y,
                    r2.x + l2.x, r2.y + l2.y, r3.x + l3.x, r3.y + l3.y};

    #pragma unroll
    for (int j = 0; j < 8; j++) {
        float y = (v[j] - mu) * rs * g0[c + j] + be0[c + j] + res[j];
        v[j] = fmaxf(y, 0.0f);
    }
    uint32_t hh[4], ll[4];
    #pragma unroll
    for (int p = 0; p < 4; p++) split2(v[2*p], v[2*p+1], hh[p], ll[p]);
    *(uint4*)&h1hi[(size_t)d * 256 + c] = make_uint4(hh[0], hh[1], hh[2], hh[3]);
    *(uint4*)&h1lo[(size_t)d * 256 + c] = make_uint4(ll[0], ll[1], ll[2], ll[3]);
}

// ---------------- fused GAT layer 1 ---------------------------------------------
__global__ void gat1_kernel(const int* __restrict__ csrc, const int* __restrict__ off,
                            const int* __restrict__ deg,
                            const float* __restrict__ als, const float* __restrict__ ald,
                            const float* __restrict__ xw,
                            const float* __restrict__ b1, const float* __restrict__ g1,
                            const float* __restrict__ be1,
                            __nv_bfloat16* __restrict__ h2hi, __nv_bfloat16* __restrict__ h2lo,
                            int n)
{
    int d = (blockIdx.x * blockDim.x + threadIdx.x) >> 5;
    int lane = threadIdx.x & 31;
    if (d >= n) return;
    const float aldv = ald[d];

    float ex = expf(lrelu(als[d] + aldv));
    float4 V = *(const float4*)&xw[(size_t)d * 128 + lane * 4];
    float v[4] = {V.x * ex, V.y * ex, V.z * ex, V.w * ex};
    float den = ex;

    const int start = off[d];
    const int cnt = deg[d];
    int e = 0;
    for (; e + 2 <= cnt; e += 2) {
        int s0 = csrc[start + e];
        int s1 = csrc[start + e + 1];
        float x0 = als[s0], x1 = als[s1];
        float4 a0 = *(const float4*)&xw[(size_t)s0 * 128 + lane * 4];
        float4 a1 = *(const float4*)&xw[(size_t)s1 * 128 + lane * 4];
        float e0 = expf(lrelu(x0 + aldv));
        float e1 = expf(lrelu(x1 + aldv));
        v[0] = fmaf(a0.x, e0, v[0]); v[1] = fmaf(a0.y, e0, v[1]);
        v[2] = fmaf(a0.z, e0, v[2]); v[3] = fmaf(a0.w, e0, v[3]);
        v[0] = fmaf(a1.x, e1, v[0]); v[1] = fmaf(a1.y, e1, v[1]);
        v[2] = fmaf(a1.z, e1, v[2]); v[3] = fmaf(a1.w, e1, v[3]);
        den += e0 + e1;
    }
    if (e < cnt) {
        int s = csrc[start + e];
        float exe = expf(lrelu(als[s] + aldv));
        float4 a = *(const float4*)&xw[(size_t)s * 128 + lane * 4];
        v[0] = fmaf(a.x, exe, v[0]); v[1] = fmaf(a.y, exe, v[1]);
        v[2] = fmaf(a.z, exe, v[2]); v[3] = fmaf(a.w, exe, v[3]);
        den += exe;
    }

    const float inv = 1.0f / den;
    const int c = lane * 4;
    #pragma unroll
    for (int j = 0; j < 4; j++) v[j] = v[j] * inv + b1[c + j];

    float s = v[0] + v[1] + v[2] + v[3];
    #pragma unroll
    for (int o = 16; o; o >>= 1) s += __shfl_xor_sync(0xffffffffu, s, o);
    float mu = s * (1.0f / 128.0f);
    float q = 0.f;
    #pragma unroll
    for (int j = 0; j < 4; j++) { float t = v[j] - mu; q += t * t; }
    #pragma unroll
    for (int o = 16; o; o >>= 1) q += __shfl_xor_sync(0xffffffffu, q, o);
    float rs = rsqrtf(q * (1.0f / 128.0f) + 1e-5f);

    float y0 = (v[0] - mu) * rs * g1[c + 0] + be1[c + 0];
    float y1 = (v[1] - mu) * rs * g1[c + 1] + be1[c + 1];
    float y2 = (v[2] - mu) * rs * g1[c + 2] + be1[c + 2];
    float y3 = (v[3] - mu) * rs * g1[c + 3] + be1[c + 3];
    uint32_t h0, l0, h1v, l1;
    split2(y0, y1, h0, l0);
    split2(y2, y3, h1v, l1);
    *(uint2*)&h2hi[(size_t)d * 128 + c] = make_uint2(h0, h1v);
    *(uint2*)&h2lo[(size_t)d * 128 + c] = make_uint2(l0, l1);
}

// ---------------- final L2 normalize --------------------------------------------
__global__ void norm_kernel(const float* __restrict__ in, float* __restrict__ out, int n)
{
    int w = (blockIdx.x * blockDim.x + threadIdx.x) >> 5;
    int lane = threadIdx.x & 31;
    if (w >= n) return;
    float4 v = *(const float4*)&in[(size_t)w * 128 + lane * 4];
    float q = v.x*v.x + v.y*v.y + v.z*v.z + v.w*v.w;
    #pragma unroll
    for (int o = 16; o; o >>= 1) q += __shfl_xor_sync(0xffffffffu, q, o);
    float sc = 1.0f / fmaxf(sqrtf(q), 1e-12f);
    v.x *= sc; v.y *= sc; v.z *= sc; v.w *= sc;
    *(float4*)&out[(size_t)w * 128 + lane * 4] = v;
}

// ---------------- launch ---------------------------------------------------------
static inline int cdiv(int a, int b) { return (a + b - 1) / b; }

extern "C" void kernel_launch(void* const* d_in, const int* in_sizes, int n_in,
                              void* d_out, int out_size)
{
    const float* x   = (const float*)d_in[0];
    const int*   ei  = (const int*)d_in[1];
    const float* Wp  = (const float*)d_in[2];
    const float* bp  = (const float*)d_in[3];
    const float* W0  = (const float*)d_in[4];
    const float* as0 = (const float*)d_in[5];
    const float* ad0 = (const float*)d_in[6];
    const float* b0  = (const float*)d_in[7];
    const float* W1  = (const float*)d_in[8];
    const float* as1 = (const float*)d_in[9];
    const float* ad1 = (const float*)d_in[10];
    const float* b1  = (const float*)d_in[11];
    const float* g0  = (const float*)d_in[12];
    const float* be0 = (const float*)d_in[13];
    const float* g1  = (const float*)d_in[14];
    const float* be1 = (const float*)d_in[15];
    const float* Wo  = (const float*)d_in[16];
    const float* bo  = (const float*)d_in[17];
    float* out = (float*)d_out;

    const int n = in_sizes[0] / DIM_IN;
    const int E = in_sizes[1] / 2;
    const int* src = ei;
    const int* dst = ei + E;

    float *p_xw0, *p_xw1, *p_o, *p_als0, *p_ald0, *p_als1, *p_ald1;
    int *p_deg, *p_off, *p_cursor, *p_csrc;
    __nv_bfloat16 *p_xhi, *p_xlo, *p_hhi, *p_hlo, *p_h1hi, *p_h1lo, *p_h2hi, *p_h2lo;
    __nv_bfloat16 *p_WpThi, *p_WpTlo, *p_W0Thi, *p_W0Tlo, *p_W1Thi, *p_W1Tlo, *p_WoThi, *p_WoTlo;
    cudaGetSymbolAddress((void**)&p_xw0,  g_xw0);
    cudaGetSymbolAddress((void**)&p_xw1,  g_xw1);
    cudaGetSymbolAddress((void**)&p_o,    g_o);
    cudaGetSymbolAddress((void**)&p_als0, g_als0);
    cudaGetSymbolAddress((void**)&p_ald0, g_ald0);
    cudaGetSymbolAddress((void**)&p_als1, g_als1);
    cudaGetSymbolAddress((void**)&p_ald1, g_ald1);
    cudaGetSymbolAddress((void**)&p_deg,    g_deg);
    cudaGetSymbolAddress((void**)&p_off,    g_off);
    cudaGetSymbolAddress((void**)&p_cursor, g_cursor);
    cudaGetSymbolAddress((void**)&p_csrc,   g_csrc);
    cudaGetSymbolAddress((void**)&p_xhi,  g_xhi);
    cudaGetSymbolAddress((void**)&p_xlo,  g_xlo);
    cudaGetSymbolAddress((void**)&p_hhi,  g_hhi);
    cudaGetSymbolAddress((void**)&p_hlo,  g_hlo);
    cudaGetSymbolAddress((void**)&p_h1hi, g_h1hi);
    cudaGetSymbolAddress((void**)&p_h1lo, g_h1lo);
    cudaGetSymbolAddress((void**)&p_h2hi, g_h2hi);
    cudaGetSymbolAddress((void**)&p_h2lo, g_h2lo);
    cudaGetSymbolAddress((void**)&p_WpThi, g_WpThi);
    cudaGetSymbolAddress((void**)&p_WpTlo, g_WpTlo);
    cudaGetSymbolAddress((void**)&p_W0Thi, g_W0Thi);
    cudaGetSymbolAddress((void**)&p_W0Tlo, g_W0Tlo);
    cudaGetSymbolAddress((void**)&p_W1Thi, g_W1Thi);
    cudaGetSymbolAddress((void**)&p_W1Tlo, g_W1Tlo);
    cudaGetSymbolAddress((void**)&p_WoThi, g_WoThi);
    cudaGetSymbolAddress((void**)&p_WoTlo, g_WoTlo);

    constexpr int SMEM_MM = 2 * 4 * 128 * 72 * 2;   // 147456 bytes
    cudaFuncSetAttribute(mm_mma<0>, cudaFuncAttributeMaxDynamicSharedMemorySize, SMEM_MM);
    cudaFuncSetAttribute(mm_mma<1>, cudaFuncAttributeMaxDynamicSharedMemorySize, SMEM_MM);
    cudaFuncSetAttribute(mm_mma<3>, cudaFuncAttributeMaxDynamicSharedMemorySize, SMEM_MM);

    const dim3 blk(256);
    const int nodeWarpBlocks = cdiv(n * 32, 256);
    const int edge4Blocks = cdiv(E / 4 + 1, 256);
    const int mrows = cdiv(n, 128);

    // ---- CSR build ----
    zero_kernel<<<cdiv(n, 256), blk>>>(p_deg, n);
    hist_kernel<<<edge4Blocks, blk>>>(dst, p_deg, E);
    scan_kernel<<<1, 1024>>>(p_deg, p_off, p_cursor, n);
    scatter_kernel<<<edge4Blocks, blk>>>(src, dst, p_cursor, p_csrc, E);

    // ---- prep splits ----
    tsplit_kernel<<<cdiv(DIM_IN * DIM_HID, 256), blk>>>(Wp, p_WpThi, p_WpTlo, DIM_IN, DIM_HID);
    tsplit_kernel<<<cdiv(DIM_HID * DIM_HID, 256), blk>>>(W0, p_W0Thi, p_W0Tlo, DIM_HID, DIM_HID);
    tsplit_kernel<<<cdiv(DIM_HID * DIM_OUT, 256), blk>>>(W1, p_W1Thi, p_W1Tlo, DIM_HID, DIM_OUT);
    tsplit_kernel<<<cdiv(DIM_OUT * DIM_OUT, 256), blk>>>(Wo, p_WoThi, p_WoTlo, DIM_OUT, DIM_OUT);
    split_kernel<<<cdiv(n * DIM_IN / 4, 256), blk>>>(x, p_xhi, p_xlo, n * DIM_IN / 4);

    // 1) h = relu(x @ Wp + bp) -> bf16 hi/lo
    mm_mma<3><<<dim3(DIM_HID / 128, mrows), blk, SMEM_MM>>>(
        p_xhi, p_xlo, p_WpThi, p_WpTlo, bp, nullptr, p_hhi, p_hlo, n, DIM_HID, DIM_IN);
    // 2) xw0 = h @ W0 (fp32)
    mm_mma<0><<<dim3(DIM_HID / 128, mrows), blk, SMEM_MM>>>(
        p_hhi, p_hlo, p_W0Thi, p_W0Tlo, nullptr, p_xw0, nullptr, nullptr, n, DIM_HID, DIM_HID);
    // 3-4) layer 0
    al0_kernel<<<nodeWarpBlocks, blk>>>(p_xw0, as0, ad0, p_als0, p_ald0, n);
    gat0_kernel<<<nodeWarpBlocks, blk>>>(p_csrc, p_off, p_deg, p_als0, p_ald0, p_xw0,
                                         p_hhi, p_hlo, b0, g0, be0, p_h1hi, p_h1lo, n);

    // 5) xw1 = h1 @ W1
    mm_mma<0><<<dim3(DIM_OUT / 128, mrows), blk, SMEM_MM>>>(
        p_h1hi, p_h1lo, p_W1Thi, p_W1Tlo, nullptr, p_xw1, nullptr, nullptr, n, DIM_OUT, DIM_HID);
    // 6-7) layer 1
    al1_kernel<<<nodeWarpBlocks, blk>>>(p_xw1, as1, ad1, p_als1, p_ald1, n);
    gat1_kernel<<<nodeWarpBlocks, blk>>>(p_csrc, p_off, p_deg, p_als1, p_ald1, p_xw1,
                                         b1, g1, be1, p_h2hi, p_h2lo, n);

    // 8) o = h2 @ Wo + bo
    mm_mma<1><<<dim3(DIM_OUT / 128, mrows), blk, SMEM_MM>>>(
        p_h2hi, p_h2lo, p_WoThi, p_WoTlo, bo, p_o, nullptr, nullptr, n, DIM_OUT, DIM_OUT);
    // 9) L2 normalize
    norm_kernel<<<nodeWarpBlocks, blk>>>(p_o, out, n);
}

// round 7
// speedup vs baseline: 1.9680x; 1.0100x over previous
#include <cuda_runtime.h>
#include <cuda_bf16.h>
#include <cstdint>
#include <cstddef>

#define N_NODES 50000
#define DIM_IN  256
#define DIM_HID 256
#define DIM_OUT 128
#define N_HEADS 4
#define E_MAX   800000

// ---------------- scratch -----------------------------------------------------
__device__ float g_xw0 [N_NODES * DIM_HID];
__device__ float g_xw1 [N_NODES * DIM_OUT];
__device__ float g_als0[N_NODES * N_HEADS];
__device__ float g_ald0[N_NODES * N_HEADS];
__device__ float g_als1[N_NODES];
__device__ float g_ald1[N_NODES];

// CSR by destination
__device__ int g_deg   [N_NODES];
__device__ int g_off   [N_NODES];
__device__ int g_cursor[N_NODES];
__device__ int g_csrc  [E_MAX];

// bf16 hi/lo splits
__device__ __nv_bfloat16 g_xhi [N_NODES * DIM_IN];
__device__ __nv_bfloat16 g_xlo [N_NODES * DIM_IN];
__device__ __nv_bfloat16 g_hhi [N_NODES * DIM_HID];
__device__ __nv_bfloat16 g_hlo [N_NODES * DIM_HID];
__device__ __nv_bfloat16 g_h1hi[N_NODES * DIM_HID];
__device__ __nv_bfloat16 g_h1lo[N_NODES * DIM_HID];
__device__ __nv_bfloat16 g_h2hi[N_NODES * DIM_OUT];
__device__ __nv_bfloat16 g_h2lo[N_NODES * DIM_OUT];
// transposed weights [N][K]
__device__ __nv_bfloat16 g_WpThi[DIM_HID * DIM_IN];
__device__ __nv_bfloat16 g_WpTlo[DIM_HID * DIM_IN];
__device__ __nv_bfloat16 g_W0Thi[DIM_HID * DIM_HID];
__device__ __nv_bfloat16 g_W0Tlo[DIM_HID * DIM_HID];
__device__ __nv_bfloat16 g_W1Thi[DIM_OUT * DIM_HID];
__device__ __nv_bfloat16 g_W1Tlo[DIM_OUT * DIM_HID];
__device__ __nv_bfloat16 g_WoThi[DIM_OUT * DIM_OUT];
__device__ __nv_bfloat16 g_WoTlo[DIM_OUT * DIM_OUT];

// ---------------- helpers ------------------------------------------------------
__device__ __forceinline__ float lrelu(float v) { return v > 0.0f ? v : 0.2f * v; }

__device__ __forceinline__ void split2(float a, float b, uint32_t& hi, uint32_t& lo) {
    __nv_bfloat16 ah = __float2bfloat16(a), bh = __float2bfloat16(b);
    __nv_bfloat16 al = __float2bfloat16(a - __bfloat162float(ah));
    __nv_bfloat16 bl = __float2bfloat16(b - __bfloat162float(bh));
    hi = (uint32_t)__bfloat16_as_ushort(ah) | ((uint32_t)__bfloat16_as_ushort(bh) << 16);
    lo = (uint32_t)__bfloat16_as_ushort(al) | ((uint32_t)__bfloat16_as_ushort(bl) << 16);
}

__device__ __forceinline__ float2 bf2_to_f2(uint32_t u) {
    __nv_bfloat162 t = *reinterpret_cast<__nv_bfloat162*>(&u);
    return make_float2(__bfloat162float(t.x), __bfloat162float(t.y));
}

__device__ __forceinline__ uint32_t smem_u32(const void* p) {
    uint32_t a;
    asm("{ .reg .u64 t; cvta.to.shared.u64 t, %1; cvt.u32.u64 %0, t; }" : "=r"(a) : "l"(p));
    return a;
}
__device__ __forceinline__ void cp_async16(uint32_t dst, const void* src) {
    asm volatile("cp.async.cg.shared.global [%0], [%1], 16;" :: "r"(dst), "l"(src));
}
#define CP_COMMIT()  asm volatile("cp.async.commit_group;" ::: "memory")
#define CP_WAIT0()   asm volatile("cp.async.wait_group 0;" ::: "memory")

__device__ __forceinline__ void ldsm_x4(uint32_t& r0, uint32_t& r1, uint32_t& r2, uint32_t& r3,
                                        uint32_t addr) {
    asm volatile("ldmatrix.sync.aligned.m8n8.x4.shared.b16 {%0,%1,%2,%3}, [%4];"
                 : "=r"(r0), "=r"(r1), "=r"(r2), "=r"(r3) : "r"(addr));
}

// ---------------- prep kernels --------------------------------------------------
__global__ void split_kernel(const float* __restrict__ in,
                             __nv_bfloat16* __restrict__ hi, __nv_bfloat16* __restrict__ lo, int n4)
{
    int i = blockIdx.x * blockDim.x + threadIdx.x;
    if (i >= n4) return;
    float4 v = ((const float4*)in)[i];
    uint32_t h0, l0, h1, l1;
    split2(v.x, v.y, h0, l0);
    split2(v.z, v.w, h1, l1);
    ((uint2*)hi)[i] = make_uint2(h0, h1);
    ((uint2*)lo)[i] = make_uint2(l0, l1);
}

// one kernel transposing+splitting all 4 weight matrices
__global__ void tsplit_all_kernel(
    const float* __restrict__ Wp, __nv_bfloat16* __restrict__ WpThi, __nv_bfloat16* __restrict__ WpTlo,
    const float* __restrict__ W0, __nv_bfloat16* __restrict__ W0Thi, __nv_bfloat16* __restrict__ W0Tlo,
    const float* __restrict__ W1, __nv_bfloat16* __restrict__ W1Thi, __nv_bfloat16* __restrict__ W1Tlo,
    const float* __restrict__ Wo, __nv_bfloat16* __restrict__ WoThi, __nv_bfloat16* __restrict__ WoTlo)
{
    const int S0 = DIM_IN * DIM_HID;            // 65536
    const int S1 = S0 + DIM_HID * DIM_HID;      // 131072
    const int S2 = S1 + DIM_HID * DIM_OUT;      // 163840
    const int S3 = S2 + DIM_OUT * DIM_OUT;      // 180224
    int gi = blockIdx.x * blockDim.x + threadIdx.x;
    if (gi >= S3) return;
    const float* W; __nv_bfloat16* Thi; __nv_bfloat16* Tlo; int K, N, idx;
    if (gi < S0)      { W = Wp; Thi = WpThi; Tlo = WpTlo; K = DIM_IN;  N = DIM_HID; idx = gi; }
    else if (gi < S1) { W = W0; Thi = W0Thi; Tlo = W0Tlo; K = DIM_HID; N = DIM_HID; idx = gi - S0; }
    else if (gi < S2) { W = W1; Thi = W1Thi; Tlo = W1Tlo; K = DIM_HID; N = DIM_OUT; idx = gi - S1; }
    else              { W = Wo; Thi = WoThi; Tlo = WoTlo; K = DIM_OUT; N = DIM_OUT; idx = gi - S2; }
    int k = idx / N, nn = idx % N;
    float v = W[idx];
    __nv_bfloat16 h = __float2bfloat16(v);
    __nv_bfloat16 l = __float2bfloat16(v - __bfloat162float(h));
    Thi[(size_t)nn * K + k] = h;
    Tlo[(size_t)nn * K + k] = l;
}

// ---------------- CSR build ------------------------------------------------------
__global__ void zero_kernel(int* __restrict__ p, int n)
{
    int i = blockIdx.x * blockDim.x + threadIdx.x;
    if (i < n) p[i] = 0;
}

__global__ void hist_kernel(const int* __restrict__ dst, int* __restrict__ deg, int E)
{
    int i = blockIdx.x * blockDim.x + threadIdx.x;
    int e4 = E >> 2;
    if (i < e4) {
        int4 d = ((const int4*)dst)[i];
        atomicAdd(&deg[d.x], 1);
        atomicAdd(&deg[d.y], 1);
        atomicAdd(&deg[d.z], 1);
        atomicAdd(&deg[d.w], 1);
    } else if (i == e4) {
        for (int t = e4 * 4; t < E; t++) atomicAdd(&deg[dst[t]], 1);
    }
}

__global__ void scan_kernel(const int* __restrict__ deg, int* __restrict__ off,
                            int* __restrict__ cursor, int n)
{
    __shared__ int wsum[32];
    __shared__ int carry_sh;
    const int tid = threadIdx.x;
    const int lane = tid & 31;
    const int wid = tid >> 5;
    if (tid == 0) carry_sh = 0;
    __syncthreads();
    for (int base = 0; base < n; base += 1024) {
        int i = base + tid;
        int v = (i < n) ? deg[i] : 0;
        int x = v;
        #pragma unroll
        for (int o = 1; o < 32; o <<= 1) {
            int t = __shfl_up_sync(0xffffffffu, x, o);
            if (lane >= o) x += t;
        }
        if (lane == 31) wsum[wid] = x;
        __syncthreads();
        if (wid == 0) {
            int s = wsum[lane];
            #pragma unroll
            for (int o = 1; o < 32; o <<= 1) {
                int t = __shfl_up_sync(0xffffffffu, s, o);
                if (lane >= o) s += t;
            }
            wsum[lane] = s;
        }
        __syncthreads();
        int warpoff = (wid > 0) ? wsum[wid - 1] : 0;
        int excl = x - v + warpoff + carry_sh;
        if (i < n) { off[i] = excl; cursor[i] = excl; }
        __syncthreads();
        if (tid == 0) carry_sh += wsum[31];
        __syncthreads();
    }
}

__global__ void scatter_kernel(const int* __restrict__ src, const int* __restrict__ dst,
                               int* __restrict__ cursor, int* __restrict__ csrc, int E)
{
    int i = blockIdx.x * blockDim.x + threadIdx.x;
    int e4 = E >> 2;
    if (i < e4) {
        int4 s = ((const int4*)src)[i];
        int4 d = ((const int4*)dst)[i];
        csrc[atomicAdd(&cursor[d.x], 1)] = s.x;
        csrc[atomicAdd(&cursor[d.y], 1)] = s.y;
        csrc[atomicAdd(&cursor[d.z], 1)] = s.z;
        csrc[atomicAdd(&cursor[d.w], 1)] = s.w;
    } else if (i == e4) {
        for (int t = e4 * 4; t < E; t++)
            csrc[atomicAdd(&cursor[dst[t]], 1)] = src[t];
    }
}

// ---------------- mma.sync split-precision GEMM, BM=128 BN=128 BK=64 ------------
// EPI: 3 relu(+bias) -> bf16 hi/lo only
//      4 fp32 C + fused attention logits (multi-head, 64-col heads)
//      5 fp32 C + fused attention logits (single head over 128 cols)
//      6 (+bias) + fused row L2-normalize -> C (= final output)
template <int EPI>
__global__ void __launch_bounds__(256, 1) mm_mma(
    const __nv_bfloat16* __restrict__ Ahi, const __nv_bfloat16* __restrict__ Alo,
    const __nv_bfloat16* __restrict__ Bhi, const __nv_bfloat16* __restrict__ Blo,
    const float* __restrict__ bias, float* __restrict__ C,
    __nv_bfloat16* __restrict__ Chi, __nv_bfloat16* __restrict__ Clo,
    const float* __restrict__ aS, const float* __restrict__ aD,
    float* __restrict__ alsOut, float* __restrict__ aldOut,
    int M, int Ntot, int K)
{
    constexpr int LDE = 72;
    constexpr int OFF_AHI = 0;
    constexpr int OFF_ALO = 128 * LDE;
    constexpr int OFF_BHI = 2 * 128 * LDE;
    constexpr int OFF_BLO = 3 * 128 * LDE;
    constexpr int STAGE   = 4 * 128 * LDE;

    extern __shared__ __nv_bfloat16 sm[];
    const uint32_t sm_base = smem_u32(sm);

    const int tid  = threadIdx.x;
    const int wid  = tid >> 5;
    const int lane = tid & 31;
    const int wm   = wid & 1;
    const int wn   = wid >> 1;
    const int m0   = blockIdx.y * 128;
    const int n0   = blockIdx.x * 128;
    const int nk   = K >> 6;

    auto load_stage = [&](int kc, int st) {
        const int k0 = kc * 64;
        const uint32_t sbase = sm_base + (uint32_t)(st * STAGE) * 2;
        #pragma unroll
        for (int c = 0; c < 4; c++) {
            int idx = c * 256 + tid;
            int row = idx >> 3, seg = idx & 7;
            uint32_t doff = (uint32_t)(row * LDE + seg * 8) * 2;
            int gm = m0 + row;
            if (gm < M) {
                cp_async16(sbase + OFF_AHI * 2 + doff, &Ahi[(size_t)gm * K + k0 + seg * 8]);
                cp_async16(sbase + OFF_ALO * 2 + doff, &Alo[(size_t)gm * K + k0 + seg * 8]);
            } else {
                uint4 z = make_uint4(0, 0, 0, 0);
                *(uint4*)(sm + st * STAGE + OFF_AHI + row * LDE + seg * 8) = z;
                *(uint4*)(sm + st * STAGE + OFF_ALO + row * LDE + seg * 8) = z;
            }
            const size_t goff = (size_t)(n0 + row) * K + k0 + seg * 8;
            cp_async16(sbase + OFF_BHI * 2 + doff, &Bhi[goff]);
            cp_async16(sbase + OFF_BLO * 2 + doff, &Blo[goff]);
        }
        CP_COMMIT();
    };

    float4 acc[4][4];
    #pragma unroll
    for (int i = 0; i < 4; i++)
        #pragma unroll
        for (int j = 0; j < 4; j++) acc[i][j] = make_float4(0.f, 0.f, 0.f, 0.f);

    load_stage(0, 0);

    const int l7 = lane & 7;
    const int a_rq = ((lane >> 3) & 1) * 8;
    const int a_kq = (lane >> 4) * 8;
    const int b_rq = (lane >> 4) * 8;
    const int b_kq = ((lane >> 3) & 1) * 8;

    for (int kc = 0; kc < nk; kc++) {
        const int st = kc & 1;
        CP_WAIT0();
        __syncthreads();
        if (kc + 1 < nk) load_stage(kc + 1, st ^ 1);

        const uint32_t sst = sm_base + (uint32_t)(st * STAGE) * 2;

        #pragma unroll
        for (int kk = 0; kk < 4; kk++) {
            const int k0b = kk * 16;
            uint32_t ahi[4][4], alo[4][4], bhi[4][2], blo[4][2];
            #pragma unroll
            for (int mt = 0; mt < 4; mt++) {
                int arow = wm * 64 + mt * 16 + l7 + a_rq;
                uint32_t ad = sst + (uint32_t)(OFF_AHI + arow * LDE + k0b + a_kq) * 2;
                ldsm_x4(ahi[mt][0], ahi[mt][1], ahi[mt][2], ahi[mt][3], ad);
                uint32_t ad2 = sst + (uint32_t)(OFF_ALO + arow * LDE + k0b + a_kq) * 2;
                ldsm_x4(alo[mt][0], alo[mt][1], alo[mt][2], alo[mt][3], ad2);
            }
            #pragma unroll
            for (int np = 0; np < 2; np++) {
                int brow = wn * 32 + np * 16 + l7 + b_rq;
                uint32_t bd = sst + (uint32_t)(OFF_BHI + brow * LDE + k0b + b_kq) * 2;
                ldsm_x4(bhi[2*np][0], bhi[2*np][1], bhi[2*np+1][0], bhi[2*np+1][1], bd);
                uint32_t bd2 = sst + (uint32_t)(OFF_BLO + brow * LDE + k0b + b_kq) * 2;
                ldsm_x4(blo[2*np][0], blo[2*np][1], blo[2*np+1][0], blo[2*np+1][1], bd2);
            }
            #pragma unroll
            for (int mt = 0; mt < 4; mt++)
                #pragma unroll
                for (int nt = 0; nt < 4; nt++) {
                    float4& d = acc[mt][nt];
                    asm volatile(
                        "mma.sync.aligned.m16n8k16.row.col.f32.bf16.bf16.f32 "
                        "{%0,%1,%2,%3},{%4,%5,%6,%7},{%8,%9},{%0,%1,%2,%3};"
                        : "+f"(d.x), "+f"(d.y), "+f"(d.z), "+f"(d.w)
                        : "r"(ahi[mt][0]), "r"(ahi[mt][1]), "r"(ahi[mt][2]), "r"(ahi[mt][3]),
                          "r"(bhi[nt][0]), "r"(bhi[nt][1]));
                    asm volatile(
                        "mma.sync.aligned.m16n8k16.row.col.f32.bf16.bf16.f32 "
                        "{%0,%1,%2,%3},{%4,%5,%6,%7},{%8,%9},{%0,%1,%2,%3};"
                        : "+f"(d.x), "+f"(d.y), "+f"(d.z), "+f"(d.w)
                        : "r"(ahi[mt][0]), "r"(ahi[mt][1]), "r"(ahi[mt][2]), "r"(ahi[mt][3]),
                          "r"(blo[nt][0]), "r"(blo[nt][1]));
                    asm volatile(
                        "mma.sync.aligned.m16n8k16.row.col.f32.bf16.bf16.f32 "
                        "{%0,%1,%2,%3},{%4,%5,%6,%7},{%8,%9},{%0,%1,%2,%3};"
                        : "+f"(d.x), "+f"(d.y), "+f"(d.z), "+f"(d.w)
                        : "r"(alo[mt][0]), "r"(alo[mt][1]), "r"(alo[mt][2]), "r"(alo[mt][3]),
                          "r"(bhi[nt][0]), "r"(bhi[nt][1]));
                }
        }
        __syncthreads();
    }

    // ============================ epilogue ============================
    float* sred = (float*)sm;   // smem reuse after last __syncthreads()

    if (EPI == 3) {
        #pragma unroll
        for (int mt = 0; mt < 4; mt++) {
            #pragma unroll
            for (int nt = 0; nt < 4; nt++) {
                float4 d = acc[mt][nt];
                int r0  = m0 + wm * 64 + mt * 16 + (lane >> 2);
                int col = n0 + wn * 32 + nt * 8 + (lane & 3) * 2;
                float bv0 = bias[col], bv1 = bias[col + 1];
                d.x = fmaxf(d.x + bv0, 0.f); d.y = fmaxf(d.y + bv1, 0.f);
                d.z = fmaxf(d.z + bv0, 0.f); d.w = fmaxf(d.w + bv1, 0.f);
                uint32_t h, l;
                if (r0 < M) {
                    split2(d.x, d.y, h, l);
                    *(uint32_t*)&Chi[(size_t)r0 * Ntot + col] = h;
                    *(uint32_t*)&Clo[(size_t)r0 * Ntot + col] = l;
                }
                if (r0 + 8 < M) {
                    split2(d.z, d.w, h, l);
                    *(uint32_t*)&Chi[(size_t)(r0 + 8) * Ntot + col] = h;
                    *(uint32_t*)&Clo[(size_t)(r0 + 8) * Ntot + col] = l;
                }
            }
        }
    }

    if (EPI == 4 || EPI == 5) {
        // sred[0..255] = als partials [row][hl], sred[256..511] = ald partials
        if (tid < 256) { sred[tid] = 0.f; sred[256 + tid] = 0.f; }
        __syncthreads();
        const int hl = wn >> 1;  // warp's 32 cols lie within one 64-col half
        #pragma unroll
        for (int mt = 0; mt < 4; mt++) {
            float psA = 0.f, pdA = 0.f, psB = 0.f, pdB = 0.f;
            int lr  = wm * 64 + mt * 16 + (lane >> 2);
            #pragma unroll
            for (int nt = 0; nt < 4; nt++) {
                float4 d = acc[mt][nt];
                int col = n0 + wn * 32 + nt * 8 + (lane & 3) * 2;
                int r0 = m0 + lr;
                if (r0 < M)
                    *(float2*)&C[(size_t)r0 * Ntot + col] = make_float2(d.x, d.y);
                if (r0 + 8 < M)
                    *(float2*)&C[(size_t)(r0 + 8) * Ntot + col] = make_float2(d.z, d.w);
                float s0 = aS[col], s1 = aS[col + 1];
                float q0 = aD[col], q1 = aD[col + 1];
                psA += d.x * s0 + d.y * s1;  pdA += d.x * q0 + d.y * q1;
                psB += d.z * s0 + d.w * s1;  pdB += d.z * q0 + d.w * q1;
            }
            // reduce over lane&3 (same rows, different cols)
            #pragma unroll
            for (int o = 1; o <= 2; o <<= 1) {
                psA += __shfl_xor_sync(0xffffffffu, psA, o);
                pdA += __shfl_xor_sync(0xffffffffu, pdA, o);
                psB += __shfl_xor_sync(0xffffffffu, psB, o);
                pdB += __shfl_xor_sync(0xffffffffu, pdB, o);
            }
            if ((lane & 3) == 0) {
                atomicAdd(&sred[lr * 2 + hl], psA);
                atomicAdd(&sred[256 + lr * 2 + hl], pdA);
                atomicAdd(&sred[(lr + 8) * 2 + hl], psB);
                atomicAdd(&sred[256 + (lr + 8) * 2 + hl], pdB);
            }
        }
        __syncthreads();
        if (EPI == 4) {
            if (tid < 256) {
                int row = tid >> 1, h = tid & 1;
                int gm = m0 + row;
                if (gm < M) {
                    int head = (n0 >> 6) + h;
                    alsOut[(size_t)gm * 4 + head] = sred[tid];
                    aldOut[(size_t)gm * 4 + head] = sred[256 + tid];
                }
            }
        } else {  // EPI 5: single head spans both halves
            if (tid < 128) {
                int gm = m0 + tid;
                if (gm < M) {
                    alsOut[gm] = sred[tid * 2] + sred[tid * 2 + 1];
                    aldOut[gm] = sred[256 + tid * 2] + sred[256 + tid * 2 + 1];
                }
            }
        }
    }

    if (EPI == 6) {
        // pass 1: add bias into acc, accumulate row sum-of-squares
        if (tid < 128) sred[tid] = 0.f;
        __syncthreads();
        #pragma unroll
        for (int mt = 0; mt < 4; mt++) {
            float qA = 0.f, qB = 0.f;
            int lr = wm * 64 + mt * 16 + (lane >> 2);
            #pragma unroll
            for (int nt = 0; nt < 4; nt++) {
                float4& d = acc[mt][nt];
                int col = n0 + wn * 32 + nt * 8 + (lane & 3) * 2;
                float bv0 = bias[col], bv1 = bias[col + 1];
                d.x += bv0; d.y += bv1; d.z += bv0; d.w += bv1;
                qA += d.x * d.x + d.y * d.y;
                qB += d.z * d.z + d.w * d.w;
            }
            #pragma unroll
            for (int o = 1; o <= 2; o <<= 1) {
                qA += __shfl_xor_sync(0xffffffffu, qA, o);
                qB += __shfl_xor_sync(0xffffffffu, qB, o);
            }
            if ((lane & 3) == 0) {
                atomicAdd(&sred[lr], qA);
                atomicAdd(&sred[lr + 8], qB);
            }
        }
        __syncthreads();
        #pragma unroll
        for (int mt = 0; mt < 4; mt++) {
            int lr = wm * 64 + mt * 16 + (lane >> 2);
            float scA = 1.0f / fmaxf(sqrtf(sred[lr]), 1e-12f);
            float scB = 1.0f / fmaxf(sqrtf(sred[lr + 8]), 1e-12f);
            #pragma unroll
            for (int nt = 0; nt < 4; nt++) {
                float4 d = acc[mt][nt];
                int col = n0 + wn * 32 + nt * 8 + (lane & 3) * 2;
                int r0 = m0 + lr;
                if (r0 < M)
                    *(float2*)&C[(size_t)r0 * Ntot + col] = make_float2(d.x * scA, d.y * scA);
                if (r0 + 8 < M)
                    *(float2*)&C[(size_t)(r0 + 8) * Ntot + col] = make_float2(d.z * scB, d.w * scB);
            }
        }
    }
}

// ---------------- fused GAT layer 0 ---------------------------------------------
__global__ void gat0_kernel(const int* __restrict__ csrc, const int* __restrict__ off,
                            const int* __restrict__ deg,
                            const float* __restrict__ als, const float* __restrict__ ald,
                            const float* __restrict__ xw,
                            const __nv_bfloat16* __restrict__ hhi,
                            const __nv_bfloat16* __restrict__ hlo,
                            const float* __restrict__ b0, const float* __restrict__ g0,
                            const float* __restrict__ be0,
                            __nv_bfloat16* __restrict__ h1hi, __nv_bfloat16* __restrict__ h1lo,
                            int n)
{
    int d = (blockIdx.x * blockDim.x + threadIdx.x) >> 5;
    int lane = threadIdx.x & 31;
    if (d >= n) return;
    const int head = lane >> 3;
    const float aldv = ald[(size_t)d * 4 + head];

    float ex = expf(lrelu(als[(size_t)d * 4 + head] + aldv));
    const float4* xp = (const float4*)&xw[(size_t)d * 256 + lane * 8];
    float4 A = xp[0], B = xp[1];
    float v[8] = {A.x * ex, A.y * ex, A.z * ex, A.w * ex,
                  B.x * ex, B.y * ex, B.z * ex, B.w * ex};
    float den = ex;

    const int start = off[d];
    const int cnt = deg[d];
    int e = 0;
    for (; e + 4 <= cnt; e += 4) {
        int s0 = csrc[start + e + 0];
        int s1 = csrc[start + e + 1];
        int s2 = csrc[start + e + 2];
        int s3 = csrc[start + e + 3];
        float x0 = als[(size_t)s0 * 4 + head];
        float x1 = als[(size_t)s1 * 4 + head];
        float x2 = als[(size_t)s2 * 4 + head];
        float x3 = als[(size_t)s3 * 4 + head];
        const float4* p0 = (const float4*)&xw[(size_t)s0 * 256 + lane * 8];
        const float4* p1 = (const float4*)&xw[(size_t)s1 * 256 + lane * 8];
        const float4* p2 = (const float4*)&xw[(size_t)s2 * 256 + lane * 8];
        const float4* p3 = (const float4*)&xw[(size_t)s3 * 256 + lane * 8];
        float4 a0 = p0[0], c0 = p0[1];
        float4 a1 = p1[0], c1 = p1[1];
        float4 a2 = p2[0], c2 = p2[1];
        float4 a3 = p3[0], c3 = p3[1];
        float e0 = expf(lrelu(x0 + aldv));
        float e1 = expf(lrelu(x1 + aldv));
        float e2 = expf(lrelu(x2 + aldv));
        float e3 = expf(lrelu(x3 + aldv));
        v[0] = fmaf(a0.x, e0, v[0]); v[1] = fmaf(a0.y, e0, v[1]);
        v[2] = fmaf(a0.z, e0, v[2]); v[3] = fmaf(a0.w, e0, v[3]);
        v[4] = fmaf(c0.x, e0, v[4]); v[5] = fmaf(c0.y, e0, v[5]);
        v[6] = fmaf(c0.z, e0, v[6]); v[7] = fmaf(c0.w, e0, v[7]);
        v[0] = fmaf(a1.x, e1, v[0]); v[1] = fmaf(a1.y, e1, v[1]);
        v[2] = fmaf(a1.z, e1, v[2]); v[3] = fmaf(a1.w, e1, v[3]);
        v[4] = fmaf(c1.x, e1, v[4]); v[5] = fmaf(c1.y, e1, v[5]);
        v[6] = fmaf(c1.z, e1, v[6]); v[7] = fmaf(c1.w, e1, v[7]);
        v[0] = fmaf(a2.x, e2, v[0]); v[1] = fmaf(a2.y, e2, v[1]);
        v[2] = fmaf(a2.z, e2, v[2]); v[3] = fmaf(a2.w, e2, v[3]);
        v[4] = fmaf(c2.x, e2, v[4]); v[5] = fmaf(c2.y, e2, v[5]);
        v[6] = fmaf(c2.z, e2, v[6]); v[7] = fmaf(c2.w, e2, v[7]);
        v[0] = fmaf(a3.x, e3, v[0]); v[1] = fmaf(a3.y, e3, v[1]);
        v[2] = fmaf(a3.z, e3, v[2]); v[3] = fmaf(a3.w, e3, v[3]);
        v[4] = fmaf(c3.x, e3, v[4]); v[5] = fmaf(c3.y, e3, v[5]);
        v[6] = fmaf(c3.z, e3, v[6]); v[7] = fmaf(c3.w, e3, v[7]);
        den += e0 + e1 + e2 + e3;
    }
    for (; e < cnt; e++) {
        int s = csrc[start + e];
        float exe = expf(lrelu(als[(size_t)s * 4 + head] + aldv));
        const float4* sp = (const float4*)&xw[(size_t)s * 256 + lane * 8];
        float4 a = sp[0], b = sp[1];
        v[0] = fmaf(a.x, exe, v[0]); v[1] = fmaf(a.y, exe, v[1]);
        v[2] = fmaf(a.z, exe, v[2]); v[3] = fmaf(a.w, exe, v[3]);
        v[4] = fmaf(b.x, exe, v[4]); v[5] = fmaf(b.y, exe, v[5]);
        v[6] = fmaf(b.z, exe, v[6]); v[7] = fmaf(b.w, exe, v[7]);
        den += exe;
    }

    const float inv = 1.0f / den;
    const int c = lane * 8;
    #pragma unroll
    for (int j = 0; j < 8; j++) v[j] = v[j] * inv + b0[c + j];

    float s = 0.f;
    #pragma unroll
    for (int j = 0; j < 8; j++) s += v[j];
    #pragma unroll
    for (int o = 16; o; o >>= 1) s += __shfl_xor_sync(0xffffffffu, s, o);
    float mu = s * (1.0f / 256.0f);
    float q = 0.f;
    #pragma unroll
    for (int j = 0; j < 8; j++) { float t = v[j] - mu; q += t * t; }
    #pragma unroll
    for (int o = 16; o; o >>= 1) q += __shfl_xor_sync(0xffffffffu, q, o);
    float rs = rsqrtf(q * (1.0f / 256.0f) + 1e-5f);

    uint4 rh = *(const uint4*)&hhi[(size_t)d * 256 + c];
    uint4 rl = *(const uint4*)&hlo[(size_t)d * 256 + c];
    float2 r0 = bf2_to_f2(rh.x), r1 = bf2_to_f2(rh.y), r2 = bf2_to_f2(rh.z), r3 = bf2_to_f2(rh.w);
    float2 l0 = bf2_to_f2(rl.x), l1 = bf2_to_f2(rl.y), l2 = bf2_to_f2(rl.z), l3 = bf2_to_f2(rl.w);
    float res[8] = {r0.x + l0.x, r0.y + l0.y, r1.x + l1.x, r1.y + l1.y,
                    r2.x + l2.x, r2.y + l2.y, r3.x + l3.x, r3.y + l3.y};

    #pragma unroll
    for (int j = 0; j < 8; j++) {
        float y = (v[j] - mu) * rs * g0[c + j] + be0[c + j] + res[j];
        v[j] = fmaxf(y, 0.0f);
    }
    uint32_t hh[4], ll[4];
    #pragma unroll
    for (int p = 0; p < 4; p++) split2(v[2*p], v[2*p+1], hh[p], ll[p]);
    *(uint4*)&h1hi[(size_t)d * 256 + c] = make_uint4(hh[0], hh[1], hh[2], hh[3]);
    *(uint4*)&h1lo[(size_t)d * 256 + c] = make_uint4(ll[0], ll[1], ll[2], ll[3]);
}

// ---------------- fused GAT layer 1 ---------------------------------------------
__global__ void gat1_kernel(const int* __restrict__ csrc, const int* __restrict__ off,
                            const int* __restrict__ deg,
                            const float* __restrict__ als, const float* __restrict__ ald,
                            const float* __restrict__ xw,
                            const float* __restrict__ b1, const float* __restrict__ g1,
                            const float* __restrict__ be1,
                            __nv_bfloat16* __restrict__ h2hi, __nv_bfloat16* __restrict__ h2lo,
                            int n)
{
    int d = (blockIdx.x * blockDim.x + threadIdx.x) >> 5;
    int lane = threadIdx.x & 31;
    if (d >= n) return;
    const float aldv = ald[d];

    float ex = expf(lrelu(als[d] + aldv));
    float4 V = *(const float4*)&xw[(size_t)d * 128 + lane * 4];
    float v[4] = {V.x * ex, V.y * ex, V.z * ex, V.w * ex};
    float den = ex;

    const int start = off[d];
    const int cnt = deg[d];
    int e = 0;
    for (; e + 4 <= cnt; e += 4) {
        int s0 = csrc[start + e + 0];
        int s1 = csrc[start + e + 1];
        int s2 = csrc[start + e + 2];
        int s3 = csrc[start + e + 3];
        float x0 = als[s0], x1 = als[s1], x2 = als[s2], x3 = als[s3];
        float4 a0 = *(const float4*)&xw[(size_t)s0 * 128 + lane * 4];
        float4 a1 = *(const float4*)&xw[(size_t)s1 * 128 + lane * 4];
        float4 a2 = *(const float4*)&xw[(size_t)s2 * 128 + lane * 4];
        float4 a3 = *(const float4*)&xw[(size_t)s3 * 128 + lane * 4];
        float e0 = expf(lrelu(x0 + aldv));
        float e1 = expf(lrelu(x1 + aldv));
        float e2 = expf(lrelu(x2 + aldv));
        float e3 = expf(lrelu(x3 + aldv));
        v[0] = fmaf(a0.x, e0, v[0]); v[1] = fmaf(a0.y, e0, v[1]);
        v[2] = fmaf(a0.z, e0, v[2]); v[3] = fmaf(a0.w, e0, v[3]);
        v[0] = fmaf(a1.x, e1, v[0]); v[1] = fmaf(a1.y, e1, v[1]);
        v[2] = fmaf(a1.z, e1, v[2]); v[3] = fmaf(a1.w, e1, v[3]);
        v[0] = fmaf(a2.x, e2, v[0]); v[1] = fmaf(a2.y, e2, v[1]);
        v[2] = fmaf(a2.z, e2, v[2]); v[3] = fmaf(a2.w, e2, v[3]);
        v[0] = fmaf(a3.x, e3, v[0]); v[1] = fmaf(a3.y, e3, v[1]);
        v[2] = fmaf(a3.z, e3, v[2]); v[3] = fmaf(a3.w, e3, v[3]);
        den += e0 + e1 + e2 + e3;
    }
    for (; e < cnt; e++) {
        int s = csrc[start + e];
        float exe = expf(lrelu(als[s] + aldv));
        float4 a = *(const float4*)&xw[(size_t)s * 128 + lane * 4];
        v[0] = fmaf(a.x, exe, v[0]); v[1] = fmaf(a.y, exe, v[1]);
        v[2] = fmaf(a.z, exe, v[2]); v[3] = fmaf(a.w, exe, v[3]);
        den += exe;
    }

    const float inv = 1.0f / den;
    const int c = lane * 4;
    #pragma unroll
    for (int j = 0; j < 4; j++) v[j] = v[j] * inv + b1[c + j];

    float s = v[0] + v[1] + v[2] + v[3];
    #pragma unroll
    for (int o = 16; o; o >>= 1) s += __shfl_xor_sync(0xffffffffu, s, o);
    float mu = s * (1.0f / 128.0f);
    float q = 0.f;
    #pragma unroll
    for (int j = 0; j < 4; j++) { float t = v[j] - mu; q += t * t; }
    #pragma unroll
    for (int o = 16; o; o >>= 1) q += __shfl_xor_sync(0xffffffffu, q, o);
    float rs = rsqrtf(q * (1.0f / 128.0f) + 1e-5f);

    float y0 = (v[0] - mu) * rs * g1[c + 0] + be1[c + 0];
    float y1 = (v[1] - mu) * rs * g1[c + 1] + be1[c + 1];
    float y2 = (v[2] - mu) * rs * g1[c + 2] + be1[c + 2];
    float y3 = (v[3] - mu) * rs * g1[c + 3] + be1[c + 3];
    uint32_t h0, l0, h1v, l1;
    split2(y0, y1, h0, l0);
    split2(y2, y3, h1v, l1);
    *(uint2*)&h2hi[(size_t)d * 128 + c] = make_uint2(h0, h1v);
    *(uint2*)&h2lo[(size_t)d * 128 + c] = make_uint2(l0, l1);
}

// ---------------- launch ---------------------------------------------------------
static inline int cdiv(int a, int b) { return (a + b - 1) / b; }

extern "C" void kernel_launch(void* const* d_in, const int* in_sizes, int n_in,
                              void* d_out, int out_size)
{
    const float* x   = (const float*)d_in[0];
    const int*   ei  = (const int*)d_in[1];
    const float* Wp  = (const float*)d_in[2];
    const float* bp  = (const float*)d_in[3];
    const float* W0  = (const float*)d_in[4];
    const float* as0 = (const float*)d_in[5];
    const float* ad0 = (const float*)d_in[6];
    const float* b0  = (const float*)d_in[7];
    const float* W1  = (const float*)d_in[8];
    const float* as1 = (const float*)d_in[9];
    const float* ad1 = (const float*)d_in[10];
    const float* b1  = (const float*)d_in[11];
    const float* g0  = (const float*)d_in[12];
    const float* be0 = (const float*)d_in[13];
    const float* g1  = (const float*)d_in[14];
    const float* be1 = (const float*)d_in[15];
    const float* Wo  = (const float*)d_in[16];
    const float* bo  = (const float*)d_in[17];
    float* out = (float*)d_out;

    const int n = in_sizes[0] / DIM_IN;
    const int E = in_sizes[1] / 2;
    const int* src = ei;
    const int* dst = ei + E;

    float *p_xw0, *p_xw1, *p_als0, *p_ald0, *p_als1, *p_ald1;
    int *p_deg, *p_off, *p_cursor, *p_csrc;
    __nv_bfloat16 *p_xhi, *p_xlo, *p_hhi, *p_hlo, *p_h1hi, *p_h1lo, *p_h2hi, *p_h2lo;
    __nv_bfloat16 *p_WpThi, *p_WpTlo, *p_W0Thi, *p_W0Tlo, *p_W1Thi, *p_W1Tlo, *p_WoThi, *p_WoTlo;
    cudaGetSymbolAddress((void**)&p_xw0,  g_xw0);
    cudaGetSymbolAddress((void**)&p_xw1,  g_xw1);
    cudaGetSymbolAddress((void**)&p_als0, g_als0);
    cudaGetSymbolAddress((void**)&p_ald0, g_ald0);
    cudaGetSymbolAddress((void**)&p_als1, g_als1);
    cudaGetSymbolAddress((void**)&p_ald1, g_ald1);
    cudaGetSymbolAddress((void**)&p_deg,    g_deg);
    cudaGetSymbolAddress((void**)&p_off,    g_off);
    cudaGetSymbolAddress((void**)&p_cursor, g_cursor);
    cudaGetSymbolAddress((void**)&p_csrc,   g_csrc);
    cudaGetSymbolAddress((void**)&p_xhi,  g_xhi);
    cudaGetSymbolAddress((void**)&p_xlo,  g_xlo);
    cudaGetSymbolAddress((void**)&p_hhi,  g_hhi);
    cudaGetSymbolAddress((void**)&p_hlo,  g_hlo);
    cudaGetSymbolAddress((void**)&p_h1hi, g_h1hi);
    cudaGetSymbolAddress((void**)&p_h1lo, g_h1lo);
    cudaGetSymbolAddress((void**)&p_h2hi, g_h2hi);
    cudaGetSymbolAddress((void**)&p_h2lo, g_h2lo);
    cudaGetSymbolAddress((void**)&p_WpThi, g_WpThi);
    cudaGetSymbolAddress((void**)&p_WpTlo, g_WpTlo);
    cudaGetSymbolAddress((void**)&p_W0Thi, g_W0Thi);
    cudaGetSymbolAddress((void**)&p_W0Tlo, g_W0Tlo);
    cudaGetSymbolAddress((void**)&p_W1Thi, g_W1Thi);
    cudaGetSymbolAddress((void**)&p_W1Tlo, g_W1Tlo);
    cudaGetSymbolAddress((void**)&p_WoThi, g_WoThi);
    cudaGetSymbolAddress((void**)&p_WoTlo, g_WoTlo);

    constexpr int SMEM_MM = 2 * 4 * 128 * 72 * 2;   // 147456 bytes
    cudaFuncSetAttribute(mm_mma<3>, cudaFuncAttributeMaxDynamicSharedMemorySize, SMEM_MM);
    cudaFuncSetAttribute(mm_mma<4>, cudaFuncAttributeMaxDynamicSharedMemorySize, SMEM_MM);
    cudaFuncSetAttribute(mm_mma<5>, cudaFuncAttributeMaxDynamicSharedMemorySize, SMEM_MM);
    cudaFuncSetAttribute(mm_mma<6>, cudaFuncAttributeMaxDynamicSharedMemorySize, SMEM_MM);

    const dim3 blk(256);
    const int nodeWarpBlocks = cdiv(n * 32, 256);
    const int edge4Blocks = cdiv(E / 4 + 1, 256);
    const int mrows = cdiv(n, 128);
    const int TSPLIT_TOT = DIM_IN*DIM_HID + DIM_HID*DIM_HID + DIM_HID*DIM_OUT + DIM_OUT*DIM_OUT;

    // 1-2) CSR histogram first (scan/scatter after the first GEMM)
    zero_kernel<<<cdiv(n, 256), blk>>>(p_deg, n);
    hist_kernel<<<edge4Blocks, blk>>>(dst, p_deg, E);
    // 3-4) splits
    tsplit_all_kernel<<<cdiv(TSPLIT_TOT, 256), blk>>>(
        Wp, p_WpThi, p_WpTlo, W0, p_W0Thi, p_W0Tlo,
        W1, p_W1Thi, p_W1Tlo, Wo, p_WoThi, p_WoTlo);
    split_kernel<<<cdiv(n * DIM_IN / 4, 256), blk>>>(x, p_xhi, p_xlo, n * DIM_IN / 4);

    // 5) h = relu(x @ Wp + bp) -> bf16 hi/lo        [profiled launch]
    mm_mma<3><<<dim3(DIM_HID / 128, mrows), blk, SMEM_MM>>>(
        p_xhi, p_xlo, p_WpThi, p_WpTlo, bp, nullptr, p_hhi, p_hlo,
        nullptr, nullptr, nullptr, nullptr, n, DIM_HID, DIM_IN);

    // 6-7) finish CSR
    scan_kernel<<<1, 1024>>>(p_deg, p_off, p_cursor, n);
    scatter_kernel<<<edge4Blocks, blk>>>(src, dst, p_cursor, p_csrc, E);

    // 8) xw0 = h @ W0 (fp32) + fused attention logits for layer 0
    mm_mma<4><<<dim3(DIM_HID / 128, mrows), blk, SMEM_MM>>>(
        p_hhi, p_hlo, p_W0Thi, p_W0Tlo, nullptr, p_xw0, nullptr, nullptr,
        as0, ad0, p_als0, p_ald0, n, DIM_HID, DIM_HID);
    // 9) fused gather-softmax-LN-residual-relu
    gat0_kernel<<<nodeWarpBlocks, blk>>>(p_csrc, p_off, p_deg, p_als0, p_ald0, p_xw0,
                                         p_hhi, p_hlo, b0, g0, be0, p_h1hi, p_h1lo, n);

    // 10) xw1 = h1 @ W1 + fused layer-1 logits
    mm_mma<5><<<dim3(DIM_OUT / 128, mrows), blk, SMEM_MM>>>(
        p_h1hi, p_h1lo, p_W1Thi, p_W1Tlo, nullptr, p_xw1, nullptr, nullptr,
        as1, ad1, p_als1, p_ald1, n, DIM_OUT, DIM_HID);
    // 11) fused layer 1
    gat1_kernel<<<nodeWarpBlocks, blk>>>(p_csrc, p_off, p_deg, p_als1, p_ald1, p_xw1,
                                         b1, g1, be1, p_h2hi, p_h2lo, n);

    // 12) out = normalize(h2 @ Wo + bo)  (norm fused into epilogue)
    mm_mma<6><<<dim3(DIM_OUT / 128, mrows), blk, SMEM_MM>>>(
        p_h2hi, p_h2lo, p_WoThi, p_WoTlo, bo, out, nullptr, nullptr,
        nullptr, nullptr, nullptr, nullptr, n, DIM_OUT, DIM_OUT);
}